// round 9
// baseline (speedup 1.0000x reference)
#include <cuda_runtime.h>
#include <cuda_fp16.h>
#include <cstdint>
#include <math.h>

// Problem constants (dataset-fixed shapes)
#define LAMBDA   1e-3f
#define KDIM     128      // k
#define DDIM     256      // d
#define NSPLIT   74       // split-K chunks (2 ntiles * 74 * 2 tensors = 296 CTAs = 2/SM)
#define KB       32       // K per mainloop stage (2 x k16 chunks)
#define NB       16       // Cholesky block size
#define ESCALE   512.0f   // power-of-2 scale so E's lo-halves stay in fp16 normal range
#define EINV     (1.0f / 512.0f)

// Scratch (device globals only)
__device__ float g_partial[2 * NSPLIT * KDIM * DDIM];   // ~19.4 MB split-K partials
__device__ float g_A[KDIM * DDIM];
__device__ float g_B[KDIM * DDIM];
__device__ float g_AAt[KDIM * KDIM];
__device__ float g_BAt[KDIM * KDIM];

// ---------------------------------------------------------------------------
// helpers
// ---------------------------------------------------------------------------
__device__ __forceinline__ uint32_t smem_u32(const void* p) {
    uint32_t a;
    asm("{ .reg .u64 t; cvta.to.shared.u64 t, %1; cvt.u32.u64 %0, t; }" : "=r"(a) : "l"(p));
    return a;
}
__device__ __forceinline__ void sts64(uint32_t a, uint32_t x, uint32_t y) {
    asm volatile("st.shared.v2.b32 [%0], {%1,%2};" :: "r"(a), "r"(x), "r"(y) : "memory");
}
__device__ __forceinline__ void ldsm_x4(uint32_t addr, uint32_t& r0, uint32_t& r1, uint32_t& r2, uint32_t& r3) {
    asm volatile("ldmatrix.sync.aligned.m8n8.x4.shared.b16 {%0,%1,%2,%3}, [%4];"
                 : "=r"(r0), "=r"(r1), "=r"(r2), "=r"(r3) : "r"(addr));
}
__device__ __forceinline__ void ldsm_x4t(uint32_t addr, uint32_t& r0, uint32_t& r1, uint32_t& r2, uint32_t& r3) {
    asm volatile("ldmatrix.sync.aligned.m8n8.x4.trans.shared.b16 {%0,%1,%2,%3}, [%4];"
                 : "=r"(r0), "=r"(r1), "=r"(r2), "=r"(r3) : "r"(addr));
}
// fp16 mma: D(16x8) += A(16x16) * B(16x8), fp32 accum
__device__ __forceinline__ void mma_f16(float* c,
                                        uint32_t a0, uint32_t a1, uint32_t a2, uint32_t a3,
                                        uint32_t b0, uint32_t b1) {
    asm volatile(
        "mma.sync.aligned.m16n8k16.row.col.f32.f16.f16.f32 "
        "{%0,%1,%2,%3}, {%4,%5,%6,%7}, {%8,%9}, {%0,%1,%2,%3};"
        : "+f"(c[0]), "+f"(c[1]), "+f"(c[2]), "+f"(c[3])
        : "r"(a0), "r"(a1), "r"(a2), "r"(a3), "r"(b0), "r"(b1));
}
// split x (4 floats) into hi/lo half2 pairs (packed uint32)
__device__ __forceinline__ void split4(const float* v, uint32_t* hi, uint32_t* lo) {
    __half2 h0 = __floats2half2_rn(v[0], v[1]);
    __half2 h1 = __floats2half2_rn(v[2], v[3]);
    float2 f0 = __half22float2(h0);
    float2 f1 = __half22float2(h1);
    __half2 l0 = __floats2half2_rn(v[0] - f0.x, v[1] - f0.y);
    __half2 l1 = __floats2half2_rn(v[2] - f1.x, v[3] - f1.y);
    hi[0] = *(uint32_t*)&h0; hi[1] = *(uint32_t*)&h1;
    lo[0] = *(uint32_t*)&l0; lo[1] = *(uint32_t*)&l1;
}

// ---------------------------------------------------------------------------
// SMEM layout per stage (verified conflict-free bank rotations):
//   A planes (hi,lo): 128 m-rows x 80B (32 k halves = 64B + 16B pad)
//   B planes (hi,lo):  32 k-rows x 272B (128 n halves = 256B + 16B pad)
// ---------------------------------------------------------------------------
#define A_ROWB   80
#define AP       (128 * A_ROWB)              // 10240 per plane
#define B_ROWB   272
#define BP       (32 * B_ROWB)               // 8704 per plane
#define STAGE    (2 * AP + 2 * BP)           // 37888
#define SMEM_GEMM (2 * STAGE)                // 75776  (x2 CTAs = 151.5 KB/SM)

// ---------------------------------------------------------------------------
// Kernel 1: 3xFP16 (Markidis split) mma.sync split-K GEMM, 2 CTAs/SM.
//   partial[z,s][128, ntile*128 .. +128] = E[z][:, k0:k1] @ F[z][k0:k1, tile]
// ---------------------------------------------------------------------------
__global__ __launch_bounds__(256, 2)
void gemm_mma(const float* __restrict__ Ex, const float* __restrict__ Fx,
              const float* __restrict__ Ey, const float* __restrict__ Fy,
              int N, int d, int Kc, int kd)
{
    extern __shared__ char smem[];
    const uint32_t sbase = smem_u32(smem);

    const int ntile = blockIdx.x;          // 0,1 -> which 128 of d=256
    const int s     = blockIdx.y;          // split-K chunk
    const int z     = blockIdx.z;          // tensor select
    const float* __restrict__ E = z ? Ey : Ex;
    const float* __restrict__ F = z ? Fy : Fx;

    const int k0 = s * Kc;
    const int k1 = min(k0 + Kc, N);
    const int nstages = (k1 - k0 + KB - 1) / KB;

    const int tid  = threadIdx.x;
    const int l    = tid & 31;
    const int wid  = tid >> 5;
    const int warpM = wid & 3;             // 4 warps over M -> 32 rows each
    const int warpN = wid >> 2;            // 2 warps over N -> 64 cols each
    const int mbase = warpM * 32;

    // ldmatrix lane address pieces
    const uint32_t a_lane = (uint32_t)((l & 15) * A_ROWB + ((l >> 4) << 4)) + (uint32_t)(mbase * A_ROWB);
    const uint32_t b_lane = (uint32_t)((l & 15) * B_ROWB + ((l >> 4) << 4)) + (uint32_t)(warpN * 64 * 2);

    float acc[2][8][4];
    #pragma unroll
    for (int a = 0; a < 2; a++)
        #pragma unroll
        for (int b = 0; b < 8; b++)
            #pragma unroll
            for (int c = 0; c < 4; c++) acc[a][b][c] = 0.f;

    float4 ra[4], rb[4];

    // ---- prologue: load stage 0 into registers ----
    {
        const int kt = k0;
        const bool full = (kt + KB) <= k1;
        #pragma unroll
        for (int r = 0; r < 4; r++) {
            int f = tid + r * 256;
            int m = f >> 3, q = f & 7;
            if (full) {
                ra[r] = *(const float4*)(E + (size_t)m * N + kt + q * 4);
            } else {
                float tv[4];
                #pragma unroll
                for (int jj = 0; jj < 4; jj++) {
                    int kk2 = kt + q * 4 + jj;
                    tv[jj] = (kk2 < k1) ? E[(size_t)m * N + kk2] : 0.f;
                }
                ra[r] = make_float4(tv[0], tv[1], tv[2], tv[3]);
            }
        }
        #pragma unroll
        for (int r = 0; r < 4; r++) {
            int f = tid + r * 256;
            int krow = f >> 5, nq = f & 31;
            int kk2 = kt + krow;
            rb[r] = (kk2 < k1) ? *(const float4*)(F + (size_t)kk2 * d + ntile * 128 + nq * 4)
                               : make_float4(0.f, 0.f, 0.f, 0.f);
        }
    }

    for (int t = 0; t < nstages; t++) {
        const uint32_t sAh = sbase + (t & 1) * STAGE;
        const uint32_t sAl = sAh + AP;
        const uint32_t sBh = sAl + AP;
        const uint32_t sBl = sBh + BP;

        // ---- STS stage t (scale E, hi/lo split) ----
        #pragma unroll
        for (int r = 0; r < 4; r++) {
            int f = tid + r * 256;
            int m = f >> 3, q = f & 7;
            float v[4] = {ra[r].x * ESCALE, ra[r].y * ESCALE, ra[r].z * ESCALE, ra[r].w * ESCALE};
            uint32_t hi[2], lo[2];
            split4(v, hi, lo);
            uint32_t off = (uint32_t)(m * A_ROWB + q * 8);
            sts64(sAh + off, hi[0], hi[1]);
            sts64(sAl + off, lo[0], lo[1]);
        }
        #pragma unroll
        for (int r = 0; r < 4; r++) {
            int f = tid + r * 256;
            int krow = f >> 5, nq = f & 31;
            float v[4] = {rb[r].x, rb[r].y, rb[r].z, rb[r].w};
            uint32_t hi[2], lo[2];
            split4(v, hi, lo);
            uint32_t off = (uint32_t)(krow * B_ROWB + nq * 8);
            sts64(sBh + off, hi[0], hi[1]);
            sts64(sBl + off, lo[0], lo[1]);
        }
        __syncthreads();

        // ---- prefetch stage t+1 into registers ----
        if (t + 1 < nstages) {
            const int kt = k0 + (t + 1) * KB;
            const bool full = (kt + KB) <= k1;
            #pragma unroll
            for (int r = 0; r < 4; r++) {
                int f = tid + r * 256;
                int m = f >> 3, q = f & 7;
                if (full) {
                    ra[r] = *(const float4*)(E + (size_t)m * N + kt + q * 4);
                } else {
                    float tv[4];
                    #pragma unroll
                    for (int jj = 0; jj < 4; jj++) {
                        int kk2 = kt + q * 4 + jj;
                        tv[jj] = (kk2 < k1) ? E[(size_t)m * N + kk2] : 0.f;
                    }
                    ra[r] = make_float4(tv[0], tv[1], tv[2], tv[3]);
                }
            }
            #pragma unroll
            for (int r = 0; r < 4; r++) {
                int f = tid + r * 256;
                int krow = f >> 5, nq = f & 31;
                int kk2 = kt + krow;
                rb[r] = (kk2 < k1) ? *(const float4*)(F + (size_t)kk2 * d + ntile * 128 + nq * 4)
                                   : make_float4(0.f, 0.f, 0.f, 0.f);
            }
        }

        // ---- compute stage t: 2 k16 chunks ----
        #pragma unroll
        for (int kc = 0; kc < 2; kc++) {
            uint32_t ah[2][4], al[2][4];
            #pragma unroll
            for (int mt = 0; mt < 2; mt++) {
                uint32_t aoff = a_lane + (uint32_t)(mt * 16 * A_ROWB) + (uint32_t)(kc * 32);
                ldsm_x4(sAh + aoff, ah[mt][0], ah[mt][1], ah[mt][2], ah[mt][3]);
                ldsm_x4(sAl + aoff, al[mt][0], al[mt][1], al[mt][2], al[mt][3]);
            }
            const uint32_t bk = b_lane + (uint32_t)(kc * 16 * B_ROWB);
            #pragma unroll
            for (int jp = 0; jp < 4; jp++) {
                uint32_t bh[4], bl[4];
                uint32_t boff = bk + (uint32_t)(jp * 32);       // 16 n halves per pair
                ldsm_x4t(sBh + boff, bh[0], bh[1], bh[2], bh[3]);
                ldsm_x4t(sBl + boff, bl[0], bl[1], bl[2], bl[3]);
                #pragma unroll
                for (int je = 0; je < 2; je++) {               // j = 2*jp + je
                    const int j = 2 * jp + je;
                    uint32_t b0h = bh[2 * je], b1h = bh[2 * je + 1];
                    uint32_t b0l = bl[2 * je], b1l = bl[2 * je + 1];
                    mma_f16(acc[0][j], ah[0][0], ah[0][1], ah[0][2], ah[0][3], b0h, b1h);  // hh
                    mma_f16(acc[0][j], al[0][0], al[0][1], al[0][2], al[0][3], b0h, b1h);  // lh
                    mma_f16(acc[0][j], ah[0][0], ah[0][1], ah[0][2], ah[0][3], b0l, b1l);  // hl
                    mma_f16(acc[1][j], ah[1][0], ah[1][1], ah[1][2], ah[1][3], b0h, b1h);
                    mma_f16(acc[1][j], al[1][0], al[1][1], al[1][2], al[1][3], b0h, b1h);
                    mma_f16(acc[1][j], ah[1][0], ah[1][1], ah[1][2], ah[1][3], b0l, b1l);
                }
            }
        }
        __syncthreads();
    }

    // ---- epilogue: write split-K partial tile (undo ESCALE) ----
    float* P = g_partial + (size_t)(z * NSPLIT + s) * kd;
    const int rsub = l >> 2;
    const int csub = (l & 3) * 2;
    #pragma unroll
    for (int mt = 0; mt < 2; mt++) {
        #pragma unroll
        for (int j = 0; j < 8; j++) {
            int row = mbase + mt * 16 + rsub;
            int col = ntile * 128 + warpN * 64 + j * 8 + csub;
            *(float2*)(P + (size_t)row * DDIM + col) =
                make_float2(acc[mt][j][0] * EINV, acc[mt][j][1] * EINV);
            *(float2*)(P + (size_t)(row + 8) * DDIM + col) =
                make_float2(acc[mt][j][2] * EINV, acc[mt][j][3] * EINV);
        }
    }
}

// ---------------------------------------------------------------------------
// Kernel 2: deterministic split-K reduction -> g_A, g_B  ([k, d])
// ---------------------------------------------------------------------------
__global__ void reduce_partials(int kd)
{
    int idx = blockIdx.x * blockDim.x + threadIdx.x;
    if (idx >= 2 * kd) return;
    int z = idx / kd;
    int e = idx - z * kd;
    const float* P = g_partial + (size_t)z * NSPLIT * kd;
    float sum = 0.f;
    #pragma unroll 4
    for (int s = 0; s < NSPLIT; s++) sum += P[(size_t)s * kd + e];
    (z ? g_B : g_A)[e] = sum;
}

// ---------------------------------------------------------------------------
// Kernel 3: Gram matrices. AAt[i,j] = A_i . A_j ;  BAt[i,j] = B_i . A_j
// ---------------------------------------------------------------------------
__global__ __launch_bounds__(KDIM)
void gram_kernel(int k, int d)
{
    __shared__ float row[DDIM];
    const int i = blockIdx.x;
    const int z = blockIdx.y;
    const int j = threadIdx.x;
    const float* src = z ? g_B : g_A;
    for (int t = j; t < d; t += KDIM) row[t] = src[i * d + t];
    __syncthreads();
    const float* aj = g_A + j * d;
    float sum = 0.f;
    #pragma unroll 8
    for (int t = 0; t < d; t++) sum = fmaf(row[t], aj[t], sum);
    (z ? g_BAt : g_AAt)[i * k + j] = sum;
}

// ---------------------------------------------------------------------------
// Kernel 4: one CTA per output row i. Blocked Cholesky (NB=16) + fwd/bwd subs.
// ---------------------------------------------------------------------------
__global__ __launch_bounds__(512, 1)
void solve_kernel(const float* __restrict__ evx, const float* __restrict__ evy,
                  float* __restrict__ out)
{
    __shared__ float P[KDIM * (KDIM + 1) / 2];
    __shared__ float colb[NB][KDIM];
    __shared__ float yv[KDIM];
    __shared__ float invD[KDIM];

    const int i   = blockIdx.x;
    const int tid = threadIdx.x;
    const int t   = tid & 127;
    const int q   = tid >> 7;
    const int trit = t * (t + 1) / 2;

    for (int r0 = 0; r0 < KDIM; r0 += 4) {
        int r = r0 + q;
        if (t <= r) P[r * (r + 1) / 2 + t] = g_AAt[r * KDIM + t];
    }
    if (tid < KDIM) yv[tid] = g_BAt[i * KDIM + tid];
    __syncthreads();

    if (tid < KDIM) {
        float ev = evx[tid] - evy[i];
        P[trit + tid] += LAMBDA * ev * ev;
    }
    __syncthreads();

    for (int b = 0; b < KDIM / NB; b++) {
        const int j0  = b * NB;
        const int rlo = j0 + NB;

        if (tid < 32) {
            int lrow = tid & 15;
            int row = j0 + lrow;
            int trow = row * (row + 1) / 2;
            float dreg[NB];
            float myinv = 0.f;
            #pragma unroll
            for (int c = 0; c < NB; c++)
                dreg[c] = (c <= lrow) ? P[trow + j0 + c] : 0.f;

            #pragma unroll
            for (int c = 0; c < NB; c++) {
                float dc = __shfl_sync(0xffffffffu, dreg[c], c);
                float r  = rsqrtf(dc);
                if (lrow == c)      { dreg[c] = dc * r; myinv = r; }
                else if (lrow > c)  dreg[c] *= r;
                #pragma unroll
                for (int m = c + 1; m < NB; m++) {
                    float Lmc = __shfl_sync(0xffffffffu, dreg[c], m);
                    if (lrow >= m) dreg[m] -= dreg[c] * Lmc;
                }
            }
            if (tid < 16) {
                #pragma unroll
                for (int c = 0; c < NB; c++)
                    if (c <= lrow) P[trow + j0 + c] = dreg[c];
                invD[row] = myinv;
            }
        }
        __syncthreads();

        if (rlo >= KDIM) break;

        {
            int r = rlo + tid;
            if (r < KDIM) {
                int trr = r * (r + 1) / 2;
                float a[NB];
                #pragma unroll
                for (int j = 0; j < NB; j++) a[j] = P[trr + j0 + j];
                #pragma unroll
                for (int j = 0; j < NB; j++) {
                    float v = a[j];
                    int trj = (j0 + j) * (j0 + j + 1) / 2;
                    #pragma unroll
                    for (int c = 0; c < j; c++)
                        v -= a[c] * P[trj + j0 + c];
                    a[j] = v * invD[j0 + j];
                }
                #pragma unroll
                for (int j = 0; j < NB; j++) {
                    P[trr + j0 + j] = a[j];
                    colb[j][r] = a[j];
                }
            }
        }
        __syncthreads();

        if (t >= rlo) {
            float ar[NB];
            #pragma unroll
            for (int j = 0; j < NB; j++) ar[j] = colb[j][t];
            for (int c = rlo + q; c <= t; c += 4) {
                float a2 = P[trit + c];
                #pragma unroll
                for (int j = 0; j < NB; j++) a2 -= ar[j] * colb[j][c];
                P[trit + c] = a2;
            }
        }
        __syncthreads();
    }

    for (int b = 0; b < KDIM / NB; b++) {
        const int j0 = b * NB;
        if (tid < 32) {
            int lrow = tid & 15;
            int row = j0 + lrow;
            int trow = row * (row + 1) / 2;
            float yl = yv[row];
            #pragma unroll
            for (int c = 0; c < NB; c++) {
                int rc = j0 + c;
                float t2 = yl * invD[rc];
                yl = (lrow == c) ? t2 : yl;
                float yc = __shfl_sync(0xffffffffu, yl, c);
                if (lrow > c) yl -= P[trow + rc] * yc;
            }
            if (tid < 16) yv[row] = yl;
        }
        __syncthreads();
        {
            int r = j0 + NB + tid;
            if (r < KDIM) {
                int trr = r * (r + 1) / 2;
                float a2 = yv[r];
                #pragma unroll
                for (int c = 0; c < NB; c++)
                    a2 -= P[trr + j0 + c] * yv[j0 + c];
                yv[r] = a2;
            }
        }
        __syncthreads();
    }

    for (int b = KDIM / NB - 1; b >= 0; b--) {
        const int j0 = b * NB;
        if (tid < 32) {
            int lrow = tid & 15;
            int row = j0 + lrow;
            float xl = yv[row];
            #pragma unroll
            for (int c = NB - 1; c >= 0; c--) {
                int rc = j0 + c;
                int trc = rc * (rc + 1) / 2;
                float t2 = xl * invD[rc];
                xl = (lrow == c) ? t2 : xl;
                float xc = __shfl_sync(0xffffffffu, xl, c);
                if (lrow < c) xl -= P[trc + row] * xc;
            }
            if (tid < 16) yv[row] = xl;
        }
        __syncthreads();
        {
            int r = tid;
            if (r < j0) {
                float a2 = yv[r];
                #pragma unroll
                for (int c = 0; c < NB; c++) {
                    int rc = j0 + c;
                    a2 -= P[rc * (rc + 1) / 2 + r] * yv[rc];
                }
                yv[r] = a2;
            }
        }
        __syncthreads();
    }

    if (tid < KDIM) out[i * KDIM + tid] = yv[tid];
}

// ---------------------------------------------------------------------------
// Launch
// ---------------------------------------------------------------------------
extern "C" void kernel_launch(void* const* d_in, const int* in_sizes, int n_in,
                              void* d_out, int out_size)
{
    const float* feat_x = (const float*)d_in[0];
    const float* feat_y = (const float*)d_in[1];
    const float* evals_x = (const float*)d_in[2];
    const float* evals_y = (const float*)d_in[3];
    const float* Ex = (const float*)d_in[4];
    const float* Ey = (const float*)d_in[5];

    const int  k  = in_sizes[2];                  // 128
    const long N  = (long)in_sizes[4] / k;        // 200000
    const int  d  = (int)((long)in_sizes[0] / N); // 256
    const int  kd = k * d;

    int Kc = (int)((N + NSPLIT - 1) / NSPLIT);
    Kc = ((Kc + KB - 1) / KB) * KB;

    cudaFuncSetAttribute(gemm_mma, cudaFuncAttributeMaxDynamicSharedMemorySize, SMEM_GEMM);

    dim3 ggrid(2, NSPLIT, 2);
    gemm_mma<<<ggrid, 256, SMEM_GEMM>>>(Ex, feat_x, Ey, feat_y, (int)N, d, Kc, kd);

    reduce_partials<<<(2 * kd + 255) / 256, 256>>>(kd);

    gram_kernel<<<dim3(k, 2), KDIM>>>(k, d);

    solve_kernel<<<k, 512>>>(evals_x, evals_y, (float*)d_out);
}

// round 10
// speedup vs baseline: 1.0283x; 1.0283x over previous
#include <cuda_runtime.h>
#include <cuda_fp16.h>
#include <cstdint>
#include <math.h>

// Problem constants (dataset-fixed shapes)
#define LAMBDA   1e-3f
#define KDIM     128      // k
#define DDIM     256      // d
#define NSPLIT   37       // split-K chunks (2 ntiles * 37 * 2 tensors = 148 CTAs = 1 wave)
#define KB       32       // K per mainloop stage (2 x k16 chunks)
#define NB       16       // Cholesky block size
#define NITER    24       // fixed-point iterations (rho<=0.45 -> 5e-9)
#define ESCALE   512.0f   // power-of-2 scale so E's lo-halves stay in fp16 normal range
#define EINV     (1.0f / 512.0f)

// Scratch (device globals only)
__device__ float g_partial[2 * NSPLIT * KDIM * DDIM];   // ~9.7 MB split-K partials
__device__ float g_A[KDIM * DDIM];
__device__ float g_B[KDIM * DDIM];
__device__ float g_AAt[KDIM * KDIM];
__device__ float g_BAt[KDIM * KDIM];
__device__ float g_L[KDIM * (KDIM + 1) / 2];            // packed Cholesky factor of AAt
__device__ float g_invD[KDIM];                          // 1 / L_jj
__device__ float g_W[KDIM * KDIM];                      // AAt^{-1}

// ---------------------------------------------------------------------------
// helpers
// ---------------------------------------------------------------------------
__device__ __forceinline__ uint32_t smem_u32(const void* p) {
    uint32_t a;
    asm("{ .reg .u64 t; cvta.to.shared.u64 t, %1; cvt.u32.u64 %0, t; }" : "=r"(a) : "l"(p));
    return a;
}
__device__ __forceinline__ void sts64(uint32_t a, uint32_t x, uint32_t y) {
    asm volatile("st.shared.v2.b32 [%0], {%1,%2};" :: "r"(a), "r"(x), "r"(y) : "memory");
}
__device__ __forceinline__ void ldsm_x4(uint32_t addr, uint32_t& r0, uint32_t& r1, uint32_t& r2, uint32_t& r3) {
    asm volatile("ldmatrix.sync.aligned.m8n8.x4.shared.b16 {%0,%1,%2,%3}, [%4];"
                 : "=r"(r0), "=r"(r1), "=r"(r2), "=r"(r3) : "r"(addr));
}
__device__ __forceinline__ void ldsm_x4t(uint32_t addr, uint32_t& r0, uint32_t& r1, uint32_t& r2, uint32_t& r3) {
    asm volatile("ldmatrix.sync.aligned.m8n8.x4.trans.shared.b16 {%0,%1,%2,%3}, [%4];"
                 : "=r"(r0), "=r"(r1), "=r"(r2), "=r"(r3) : "r"(addr));
}
// fp16 mma: D(16x8) += A(16x16) * B(16x8), fp32 accum
__device__ __forceinline__ void mma_f16(float* c,
                                        uint32_t a0, uint32_t a1, uint32_t a2, uint32_t a3,
                                        uint32_t b0, uint32_t b1) {
    asm volatile(
        "mma.sync.aligned.m16n8k16.row.col.f32.f16.f16.f32 "
        "{%0,%1,%2,%3}, {%4,%5,%6,%7}, {%8,%9}, {%0,%1,%2,%3};"
        : "+f"(c[0]), "+f"(c[1]), "+f"(c[2]), "+f"(c[3])
        : "r"(a0), "r"(a1), "r"(a2), "r"(a3), "r"(b0), "r"(b1));
}
// split x (4 floats) into hi/lo half2 pairs (packed uint32)
__device__ __forceinline__ void split4(const float* v, uint32_t* hi, uint32_t* lo) {
    __half2 h0 = __floats2half2_rn(v[0], v[1]);
    __half2 h1 = __floats2half2_rn(v[2], v[3]);
    float2 f0 = __half22float2(h0);
    float2 f1 = __half22float2(h1);
    __half2 l0 = __floats2half2_rn(v[0] - f0.x, v[1] - f0.y);
    __half2 l1 = __floats2half2_rn(v[2] - f1.x, v[3] - f1.y);
    hi[0] = *(uint32_t*)&h0; hi[1] = *(uint32_t*)&h1;
    lo[0] = *(uint32_t*)&l0; lo[1] = *(uint32_t*)&l1;
}

// ---------------------------------------------------------------------------
// GEMM SMEM layout per stage (conflict-free bank rotations, R8 config)
// ---------------------------------------------------------------------------
#define A_ROWB   80
#define AP       (128 * A_ROWB)              // 10240 per plane
#define B_ROWB   272
#define BP       (32 * B_ROWB)               // 8704 per plane
#define STAGE    (2 * AP + 2 * BP)           // 37888
#define SMEM_GEMM (2 * STAGE)                // 75776

// ---------------------------------------------------------------------------
// Kernel 1: 3xFP16 (Markidis split) mma.sync split-K GEMM (R8 exact).
// ---------------------------------------------------------------------------
__global__ __launch_bounds__(256, 1)
void gemm_mma(const float* __restrict__ Ex, const float* __restrict__ Fx,
              const float* __restrict__ Ey, const float* __restrict__ Fy,
              int N, int d, int Kc, int kd)
{
    extern __shared__ char smem[];
    const uint32_t sbase = smem_u32(smem);

    const int ntile = blockIdx.x;
    const int s     = blockIdx.y;
    const int z     = blockIdx.z;
    const float* __restrict__ E = z ? Ey : Ex;
    const float* __restrict__ F = z ? Fy : Fx;

    const int k0 = s * Kc;
    const int k1 = min(k0 + Kc, N);
    const int nstages = (k1 - k0 + KB - 1) / KB;

    const int tid  = threadIdx.x;
    const int l    = tid & 31;
    const int wid  = tid >> 5;
    const int warpM = wid & 3;
    const int warpN = wid >> 2;
    const int mbase = warpM * 32;

    const uint32_t a_lane = (uint32_t)((l & 15) * A_ROWB + ((l >> 4) << 4)) + (uint32_t)(mbase * A_ROWB);
    const uint32_t b_lane = (uint32_t)((l & 15) * B_ROWB + ((l >> 4) << 4)) + (uint32_t)(warpN * 64 * 2);

    float acc[2][8][4];
    #pragma unroll
    for (int a = 0; a < 2; a++)
        #pragma unroll
        for (int b = 0; b < 8; b++)
            #pragma unroll
            for (int c = 0; c < 4; c++) acc[a][b][c] = 0.f;

    float4 ra[4], rb[4];

    {
        const int kt = k0;
        const bool full = (kt + KB) <= k1;
        #pragma unroll
        for (int r = 0; r < 4; r++) {
            int f = tid + r * 256;
            int m = f >> 3, q = f & 7;
            if (full) {
                ra[r] = *(const float4*)(E + (size_t)m * N + kt + q * 4);
            } else {
                float tv[4];
                #pragma unroll
                for (int jj = 0; jj < 4; jj++) {
                    int kk2 = kt + q * 4 + jj;
                    tv[jj] = (kk2 < k1) ? E[(size_t)m * N + kk2] : 0.f;
                }
                ra[r] = make_float4(tv[0], tv[1], tv[2], tv[3]);
            }
        }
        #pragma unroll
        for (int r = 0; r < 4; r++) {
            int f = tid + r * 256;
            int krow = f >> 5, nq = f & 31;
            int kk2 = kt + krow;
            rb[r] = (kk2 < k1) ? *(const float4*)(F + (size_t)kk2 * d + ntile * 128 + nq * 4)
                               : make_float4(0.f, 0.f, 0.f, 0.f);
        }
    }

    for (int t = 0; t < nstages; t++) {
        const uint32_t sAh = sbase + (t & 1) * STAGE;
        const uint32_t sAl = sAh + AP;
        const uint32_t sBh = sAl + AP;
        const uint32_t sBl = sBh + BP;

        #pragma unroll
        for (int r = 0; r < 4; r++) {
            int f = tid + r * 256;
            int m = f >> 3, q = f & 7;
            float v[4] = {ra[r].x * ESCALE, ra[r].y * ESCALE, ra[r].z * ESCALE, ra[r].w * ESCALE};
            uint32_t hi[2], lo[2];
            split4(v, hi, lo);
            uint32_t off = (uint32_t)(m * A_ROWB + q * 8);
            sts64(sAh + off, hi[0], hi[1]);
            sts64(sAl + off, lo[0], lo[1]);
        }
        #pragma unroll
        for (int r = 0; r < 4; r++) {
            int f = tid + r * 256;
            int krow = f >> 5, nq = f & 31;
            float v[4] = {rb[r].x, rb[r].y, rb[r].z, rb[r].w};
            uint32_t hi[2], lo[2];
            split4(v, hi, lo);
            uint32_t off = (uint32_t)(krow * B_ROWB + nq * 8);
            sts64(sBh + off, hi[0], hi[1]);
            sts64(sBl + off, lo[0], lo[1]);
        }
        __syncthreads();

        if (t + 1 < nstages) {
            const int kt = k0 + (t + 1) * KB;
            const bool full = (kt + KB) <= k1;
            #pragma unroll
            for (int r = 0; r < 4; r++) {
                int f = tid + r * 256;
                int m = f >> 3, q = f & 7;
                if (full) {
                    ra[r] = *(const float4*)(E + (size_t)m * N + kt + q * 4);
                } else {
                    float tv[4];
                    #pragma unroll
                    for (int jj = 0; jj < 4; jj++) {
                        int kk2 = kt + q * 4 + jj;
                        tv[jj] = (kk2 < k1) ? E[(size_t)m * N + kk2] : 0.f;
                    }
                    ra[r] = make_float4(tv[0], tv[1], tv[2], tv[3]);
                }
            }
            #pragma unroll
            for (int r = 0; r < 4; r++) {
                int f = tid + r * 256;
                int krow = f >> 5, nq = f & 31;
                int kk2 = kt + krow;
                rb[r] = (kk2 < k1) ? *(const float4*)(F + (size_t)kk2 * d + ntile * 128 + nq * 4)
                                   : make_float4(0.f, 0.f, 0.f, 0.f);
            }
        }

        #pragma unroll
        for (int kc = 0; kc < 2; kc++) {
            uint32_t ah[2][4], al[2][4];
            #pragma unroll
            for (int mt = 0; mt < 2; mt++) {
                uint32_t aoff = a_lane + (uint32_t)(mt * 16 * A_ROWB) + (uint32_t)(kc * 32);
                ldsm_x4(sAh + aoff, ah[mt][0], ah[mt][1], ah[mt][2], ah[mt][3]);
                ldsm_x4(sAl + aoff, al[mt][0], al[mt][1], al[mt][2], al[mt][3]);
            }
            const uint32_t bk = b_lane + (uint32_t)(kc * 16 * B_ROWB);
            #pragma unroll
            for (int jp = 0; jp < 4; jp++) {
                uint32_t bh[4], bl[4];
                uint32_t boff = bk + (uint32_t)(jp * 32);
                ldsm_x4t(sBh + boff, bh[0], bh[1], bh[2], bh[3]);
                ldsm_x4t(sBl + boff, bl[0], bl[1], bl[2], bl[3]);
                #pragma unroll
                for (int je = 0; je < 2; je++) {
                    const int j = 2 * jp + je;
                    uint32_t b0h = bh[2 * je], b1h = bh[2 * je + 1];
                    uint32_t b0l = bl[2 * je], b1l = bl[2 * je + 1];
                    mma_f16(acc[0][j], ah[0][0], ah[0][1], ah[0][2], ah[0][3], b0h, b1h);
                    mma_f16(acc[0][j], al[0][0], al[0][1], al[0][2], al[0][3], b0h, b1h);
                    mma_f16(acc[0][j], ah[0][0], ah[0][1], ah[0][2], ah[0][3], b0l, b1l);
                    mma_f16(acc[1][j], ah[1][0], ah[1][1], ah[1][2], ah[1][3], b0h, b1h);
                    mma_f16(acc[1][j], al[1][0], al[1][1], al[1][2], al[1][3], b0h, b1h);
                    mma_f16(acc[1][j], ah[1][0], ah[1][1], ah[1][2], ah[1][3], b0l, b1l);
                }
            }
        }
        __syncthreads();
    }

    float* P = g_partial + (size_t)(z * NSPLIT + s) * kd;
    const int rsub = l >> 2;
    const int csub = (l & 3) * 2;
    #pragma unroll
    for (int mt = 0; mt < 2; mt++) {
        #pragma unroll
        for (int j = 0; j < 8; j++) {
            int row = mbase + mt * 16 + rsub;
            int col = ntile * 128 + warpN * 64 + j * 8 + csub;
            *(float2*)(P + (size_t)row * DDIM + col) =
                make_float2(acc[mt][j][0] * EINV, acc[mt][j][1] * EINV);
            *(float2*)(P + (size_t)(row + 8) * DDIM + col) =
                make_float2(acc[mt][j][2] * EINV, acc[mt][j][3] * EINV);
        }
    }
}

// ---------------------------------------------------------------------------
// Kernel 2: deterministic split-K reduction -> g_A, g_B
// ---------------------------------------------------------------------------
__global__ void reduce_partials(int kd)
{
    int idx = blockIdx.x * blockDim.x + threadIdx.x;
    if (idx >= 2 * kd) return;
    int z = idx / kd;
    int e = idx - z * kd;
    const float* P = g_partial + (size_t)z * NSPLIT * kd;
    float sum = 0.f;
    #pragma unroll 4
    for (int s = 0; s < NSPLIT; s++) sum += P[(size_t)s * kd + e];
    (z ? g_B : g_A)[e] = sum;
}

// ---------------------------------------------------------------------------
// Kernel 3: Gram matrices
// ---------------------------------------------------------------------------
__global__ __launch_bounds__(KDIM)
void gram_kernel(int k, int d)
{
    __shared__ float row[DDIM];
    const int i = blockIdx.x;
    const int z = blockIdx.y;
    const int j = threadIdx.x;
    const float* src = z ? g_B : g_A;
    for (int t = j; t < d; t += KDIM) row[t] = src[i * d + t];
    __syncthreads();
    const float* aj = g_A + j * d;
    float sum = 0.f;
    #pragma unroll 8
    for (int t = 0; t < d; t++) sum = fmaf(row[t], aj[t], sum);
    (z ? g_BAt : g_AAt)[i * k + j] = sum;
}

// ---------------------------------------------------------------------------
// Kernel 4: ONE-TIME blocked Cholesky of AAt (single CTA) -> g_L, g_invD
// ---------------------------------------------------------------------------
__global__ __launch_bounds__(512, 1)
void chol_kernel()
{
    __shared__ float P[KDIM * (KDIM + 1) / 2];
    __shared__ float colb[NB][KDIM];
    __shared__ float invD[KDIM];

    const int tid = threadIdx.x;
    const int t   = tid & 127;
    const int q   = tid >> 7;
    const int trit = t * (t + 1) / 2;

    for (int r0 = 0; r0 < KDIM; r0 += 4) {
        int r = r0 + q;
        if (t <= r) P[r * (r + 1) / 2 + t] = g_AAt[r * KDIM + t];
    }
    __syncthreads();

    for (int b = 0; b < KDIM / NB; b++) {
        const int j0  = b * NB;
        const int rlo = j0 + NB;

        if (tid < 32) {
            int lrow = tid & 15;
            int row = j0 + lrow;
            int trow = row * (row + 1) / 2;
            float dreg[NB];
            float myinv = 0.f;
            #pragma unroll
            for (int c = 0; c < NB; c++)
                dreg[c] = (c <= lrow) ? P[trow + j0 + c] : 0.f;

            #pragma unroll
            for (int c = 0; c < NB; c++) {
                float dc = __shfl_sync(0xffffffffu, dreg[c], c);
                float r  = rsqrtf(dc);
                if (lrow == c)      { dreg[c] = dc * r; myinv = r; }
                else if (lrow > c)  dreg[c] *= r;
                #pragma unroll
                for (int m = c + 1; m < NB; m++) {
                    float Lmc = __shfl_sync(0xffffffffu, dreg[c], m);
                    if (lrow >= m) dreg[m] -= dreg[c] * Lmc;
                }
            }
            if (tid < 16) {
                #pragma unroll
                for (int c = 0; c < NB; c++)
                    if (c <= lrow) P[trow + j0 + c] = dreg[c];
                invD[row] = myinv;
            }
        }
        __syncthreads();

        if (rlo < KDIM) {
            int r = rlo + tid;
            if (r < KDIM) {
                int trr = r * (r + 1) / 2;
                float a[NB];
                #pragma unroll
                for (int j = 0; j < NB; j++) a[j] = P[trr + j0 + j];
                #pragma unroll
                for (int j = 0; j < NB; j++) {
                    float v = a[j];
                    int trj = (j0 + j) * (j0 + j + 1) / 2;
                    #pragma unroll
                    for (int c = 0; c < j; c++)
                        v -= a[c] * P[trj + j0 + c];
                    a[j] = v * invD[j0 + j];
                }
                #pragma unroll
                for (int j = 0; j < NB; j++) {
                    P[trr + j0 + j] = a[j];
                    colb[j][r] = a[j];
                }
            }
            __syncthreads();

            if (t >= rlo) {
                float ar[NB];
                #pragma unroll
                for (int j = 0; j < NB; j++) ar[j] = colb[j][t];
                for (int c = rlo + q; c <= t; c += 4) {
                    float a2 = P[trit + c];
                    #pragma unroll
                    for (int j = 0; j < NB; j++) a2 -= ar[j] * colb[j][c];
                    P[trit + c] = a2;
                }
            }
            __syncthreads();
        }
    }

    // write packed L + invD
    for (int idx = tid; idx < KDIM * (KDIM + 1) / 2; idx += 512) g_L[idx] = P[idx];
    if (tid < KDIM) g_invD[tid] = invD[tid];
}

// ---------------------------------------------------------------------------
// Kernel 5: W rows. CTA j solves AAt w = e_j (fwd/bwd via shared L) -> g_W[j,:]
// ---------------------------------------------------------------------------
__global__ __launch_bounds__(KDIM, 1)
void wcol_kernel()
{
    __shared__ float Lp[KDIM * (KDIM + 1) / 2];
    __shared__ float invD[KDIM];
    __shared__ float yv[KDIM];

    const int j   = blockIdx.x;
    const int tid = threadIdx.x;

    for (int idx = tid; idx < KDIM * (KDIM + 1) / 2; idx += KDIM) Lp[idx] = g_L[idx];
    invD[tid] = g_invD[tid];
    yv[tid] = (tid == j) ? 1.f : 0.f;
    __syncthreads();

    // forward substitution: L y = e_j  (skip all-zero leading blocks)
    for (int b = 0; b < KDIM / NB; b++) {
        const int j0 = b * NB;
        if (j0 + NB <= j) continue;     // rows < j stay zero
        if (tid < 32) {
            int lrow = tid & 15;
            int row = j0 + lrow;
            int trow = row * (row + 1) / 2;
            float yl = yv[row];
            #pragma unroll
            for (int c = 0; c < NB; c++) {
                int rc = j0 + c;
                float t2 = yl * invD[rc];
                yl = (lrow == c) ? t2 : yl;
                float yc = __shfl_sync(0xffffffffu, yl, c);
                if (lrow > c) yl -= Lp[trow + rc] * yc;
            }
            if (tid < 16) yv[row] = yl;
        }
        __syncthreads();
        {
            int r = j0 + NB + tid;
            if (r < KDIM) {
                int trr = r * (r + 1) / 2;
                float a2 = yv[r];
                #pragma unroll
                for (int c = 0; c < NB; c++)
                    a2 -= Lp[trr + j0 + c] * yv[j0 + c];
                yv[r] = a2;
            }
        }
        __syncthreads();
    }

    // backward substitution: L^T x = y
    for (int b = KDIM / NB - 1; b >= 0; b--) {
        const int j0 = b * NB;
        if (tid < 32) {
            int lrow = tid & 15;
            int row = j0 + lrow;
            float xl = yv[row];
            #pragma unroll
            for (int c = NB - 1; c >= 0; c--) {
                int rc = j0 + c;
                int trc = rc * (rc + 1) / 2;
                float t2 = xl * invD[rc];
                xl = (lrow == c) ? t2 : xl;
                float xc = __shfl_sync(0xffffffffu, xl, c);
                if (lrow < c) xl -= Lp[trc + row] * xc;
            }
            if (tid < 16) yv[row] = xl;
        }
        __syncthreads();
        {
            int r = tid;
            if (r < j0) {
                float a2 = yv[r];
                #pragma unroll
                for (int c = 0; c < NB; c++) {
                    int rc = j0 + c;
                    a2 -= Lp[rc * (rc + 1) / 2 + r] * yv[rc];
                }
                yv[r] = a2;
            }
        }
        __syncthreads();
    }

    g_W[j * KDIM + tid] = yv[tid];   // W symmetric: row j == column j
}

// ---------------------------------------------------------------------------
// Kernel 6: per-i fixed-point solve.  x = W b - W (dv ∘ x),  dv = λ(ex-ey_i)^2
// W row-quarters live in registers (32/thread); dv folded into them once.
// ---------------------------------------------------------------------------
__global__ __launch_bounds__(512, 1)
void iter_kernel(const float* __restrict__ evx, const float* __restrict__ evy,
                 float* __restrict__ out)
{
    __shared__ float xs[KDIM];
    __shared__ float x0s[KDIM];
    __shared__ float bs[KDIM];
    __shared__ float dvs[KDIM];

    const int i   = blockIdx.x;
    const int tid = threadIdx.x;
    const int j   = tid >> 2;         // output row
    const int q   = tid & 3;          // quarter of the dot product

    // W row-quarter into registers
    float w[32];
    {
        const float4* wr = (const float4*)(g_W + j * KDIM + q * 32);
        #pragma unroll
        for (int u = 0; u < 8; u++) {
            float4 v = wr[u];
            w[4 * u + 0] = v.x; w[4 * u + 1] = v.y; w[4 * u + 2] = v.z; w[4 * u + 3] = v.w;
        }
    }
    if (tid < KDIM) {
        bs[tid] = g_BAt[i * KDIM + tid];
        float ev = evx[tid] - evy[i];
        dvs[tid] = LAMBDA * ev * ev;
    }
    __syncthreads();

    // x0 = W b
    {
        float acc = 0.f;
        #pragma unroll
        for (int u = 0; u < 32; u++) acc = fmaf(w[u], bs[q * 32 + u], acc);
        acc += __shfl_xor_sync(0xffffffffu, acc, 1);
        acc += __shfl_xor_sync(0xffffffffu, acc, 2);
        if (q == 0) { x0s[j] = acc; xs[j] = acc; }
    }
    // fold dv into registers: w[u] *= dv[c]
    #pragma unroll
    for (int u = 0; u < 32; u++) w[u] *= dvs[q * 32 + u];
    __syncthreads();

    // iterate x <- x0 - W' x
    for (int it = 0; it < NITER; it++) {
        float acc = 0.f;
        #pragma unroll
        for (int u = 0; u < 32; u++) acc = fmaf(w[u], xs[q * 32 + u], acc);
        acc += __shfl_xor_sync(0xffffffffu, acc, 1);
        acc += __shfl_xor_sync(0xffffffffu, acc, 2);
        __syncthreads();                      // all reads of xs done
        if (q == 0) xs[j] = x0s[j] - acc;
        __syncthreads();
    }

    if (tid < KDIM) out[i * KDIM + tid] = xs[tid];
}

// ---------------------------------------------------------------------------
// Launch
// ---------------------------------------------------------------------------
extern "C" void kernel_launch(void* const* d_in, const int* in_sizes, int n_in,
                              void* d_out, int out_size)
{
    const float* feat_x = (const float*)d_in[0];
    const float* feat_y = (const float*)d_in[1];
    const float* evals_x = (const float*)d_in[2];
    const float* evals_y = (const float*)d_in[3];
    const float* Ex = (const float*)d_in[4];
    const float* Ey = (const float*)d_in[5];

    const int  k  = in_sizes[2];                  // 128
    const long N  = (long)in_sizes[4] / k;        // 200000
    const int  d  = (int)((long)in_sizes[0] / N); // 256
    const int  kd = k * d;

    int Kc = (int)((N + NSPLIT - 1) / NSPLIT);
    Kc = ((Kc + KB - 1) / KB) * KB;

    cudaFuncSetAttribute(gemm_mma, cudaFuncAttributeMaxDynamicSharedMemorySize, SMEM_GEMM);

    dim3 ggrid(2, NSPLIT, 2);
    gemm_mma<<<ggrid, 256, SMEM_GEMM>>>(Ex, feat_x, Ey, feat_y, (int)N, d, Kc, kd);

    reduce_partials<<<(2 * kd + 255) / 256, 256>>>(kd);

    gram_kernel<<<dim3(k, 2), KDIM>>>(k, d);

    chol_kernel<<<1, 512>>>();
    wcol_kernel<<<k, KDIM>>>();
    iter_kernel<<<k, 512>>>(evals_x, evals_y, (float*)d_out);
}

// round 11
// speedup vs baseline: 1.0576x; 1.0285x over previous
#include <cuda_runtime.h>
#include <cuda_fp16.h>
#include <cstdint>
#include <math.h>

// Problem constants (dataset-fixed shapes)
#define LAMBDA   1e-3f
#define KDIM     128      // k
#define DDIM     256      // d
#define NSPLIT   37       // split-K chunks (2 ntiles * 37 * 2 tensors = 148 CTAs = 1 wave)
#define KB       32       // K per mainloop stage (2 x k16 chunks)
#define NB       16       // Cholesky block size
#define ESCALE   512.0f   // power-of-2 scale so E's lo-halves stay in fp16 normal range
#define EINV     (1.0f / 512.0f)

// Scratch (device globals only)
__device__ float g_partial[2 * NSPLIT * KDIM * DDIM];   // ~9.7 MB split-K partials
__device__ float g_A[KDIM * DDIM];
__device__ float g_B[KDIM * DDIM];
__device__ float g_AAt[KDIM * KDIM];
__device__ float g_BAt[KDIM * KDIM];

// ---------------------------------------------------------------------------
// helpers
// ---------------------------------------------------------------------------
__device__ __forceinline__ uint32_t smem_u32(const void* p) {
    uint32_t a;
    asm("{ .reg .u64 t; cvta.to.shared.u64 t, %1; cvt.u32.u64 %0, t; }" : "=r"(a) : "l"(p));
    return a;
}
__device__ __forceinline__ void sts64(uint32_t a, uint32_t x, uint32_t y) {
    asm volatile("st.shared.v2.b32 [%0], {%1,%2};" :: "r"(a), "r"(x), "r"(y) : "memory");
}
__device__ __forceinline__ void ldsm_x4(uint32_t addr, uint32_t& r0, uint32_t& r1, uint32_t& r2, uint32_t& r3) {
    asm volatile("ldmatrix.sync.aligned.m8n8.x4.shared.b16 {%0,%1,%2,%3}, [%4];"
                 : "=r"(r0), "=r"(r1), "=r"(r2), "=r"(r3) : "r"(addr));
}
__device__ __forceinline__ void ldsm_x4t(uint32_t addr, uint32_t& r0, uint32_t& r1, uint32_t& r2, uint32_t& r3) {
    asm volatile("ldmatrix.sync.aligned.m8n8.x4.trans.shared.b16 {%0,%1,%2,%3}, [%4];"
                 : "=r"(r0), "=r"(r1), "=r"(r2), "=r"(r3) : "r"(addr));
}
// fp16 mma: D(16x8) += A(16x16) * B(16x8), fp32 accum
__device__ __forceinline__ void mma_f16(float* c,
                                        uint32_t a0, uint32_t a1, uint32_t a2, uint32_t a3,
                                        uint32_t b0, uint32_t b1) {
    asm volatile(
        "mma.sync.aligned.m16n8k16.row.col.f32.f16.f16.f32 "
        "{%0,%1,%2,%3}, {%4,%5,%6,%7}, {%8,%9}, {%0,%1,%2,%3};"
        : "+f"(c[0]), "+f"(c[1]), "+f"(c[2]), "+f"(c[3])
        : "r"(a0), "r"(a1), "r"(a2), "r"(a3), "r"(b0), "r"(b1));
}
// split x (4 floats) into hi/lo half2 pairs (packed uint32)
__device__ __forceinline__ void split4(const float* v, uint32_t* hi, uint32_t* lo) {
    __half2 h0 = __floats2half2_rn(v[0], v[1]);
    __half2 h1 = __floats2half2_rn(v[2], v[3]);
    float2 f0 = __half22float2(h0);
    float2 f1 = __half22float2(h1);
    __half2 l0 = __floats2half2_rn(v[0] - f0.x, v[1] - f0.y);
    __half2 l1 = __floats2half2_rn(v[2] - f1.x, v[3] - f1.y);
    hi[0] = *(uint32_t*)&h0; hi[1] = *(uint32_t*)&h1;
    lo[0] = *(uint32_t*)&l0; lo[1] = *(uint32_t*)&l1;
}

// ---------------------------------------------------------------------------
// GEMM SMEM layout per stage (conflict-free bank rotations, R8 config)
// ---------------------------------------------------------------------------
#define A_ROWB   80
#define AP       (128 * A_ROWB)              // 10240 per plane
#define B_ROWB   272
#define BP       (32 * B_ROWB)               // 8704 per plane
#define STAGE    (2 * AP + 2 * BP)           // 37888
#define SMEM_GEMM (2 * STAGE)                // 75776

// ---------------------------------------------------------------------------
// Kernel 1: 3xFP16 (Markidis split) mma.sync split-K GEMM.
// Phase-staggered fill: even warps [kc0, fill, kc1], odd warps [kc0, kc1, fill]
// -> tensor pipe stays fed while half the warps fill. ONE barrier per stage
// (trailing barrier is redundant with double buffering).
// ---------------------------------------------------------------------------
__global__ __launch_bounds__(256, 1)
void gemm_mma(const float* __restrict__ Ex, const float* __restrict__ Fx,
              const float* __restrict__ Ey, const float* __restrict__ Fy,
              int N, int d, int Kc, int kd)
{
    extern __shared__ char smem[];
    const uint32_t sbase = smem_u32(smem);

    const int ntile = blockIdx.x;
    const int s     = blockIdx.y;
    const int z     = blockIdx.z;
    const float* __restrict__ E = z ? Ey : Ex;
    const float* __restrict__ F = z ? Fy : Fx;

    const int k0 = s * Kc;
    const int k1 = min(k0 + Kc, N);
    const int nstages = (k1 - k0 + KB - 1) / KB;

    const int tid  = threadIdx.x;
    const int l    = tid & 31;
    const int wid  = tid >> 5;
    const int warpM = wid & 3;
    const int warpN = wid >> 2;
    const int mbase = warpM * 32;
    const bool evenw = (wid & 1) == 0;

    const uint32_t a_lane = (uint32_t)((l & 15) * A_ROWB + ((l >> 4) << 4)) + (uint32_t)(mbase * A_ROWB);
    const uint32_t b_lane = (uint32_t)((l & 15) * B_ROWB + ((l >> 4) << 4)) + (uint32_t)(warpN * 64 * 2);

    float acc[2][8][4];
    #pragma unroll
    for (int a = 0; a < 2; a++)
        #pragma unroll
        for (int b = 0; b < 8; b++)
            #pragma unroll
            for (int c = 0; c < 4; c++) acc[a][b][c] = 0.f;

    float4 ra[4], rb[4];

    // ---- LDG of stage kt into ra/rb ----
    auto do_ldg = [&](int kt) {
        const bool full = (kt + KB) <= k1;
        #pragma unroll
        for (int r = 0; r < 4; r++) {
            int f = tid + r * 256;
            int m = f >> 3, q = f & 7;
            if (full) {
                ra[r] = *(const float4*)(E + (size_t)m * N + kt + q * 4);
            } else {
                float tv[4];
                #pragma unroll
                for (int jj = 0; jj < 4; jj++) {
                    int kk2 = kt + q * 4 + jj;
                    tv[jj] = (kk2 < k1) ? E[(size_t)m * N + kk2] : 0.f;
                }
                ra[r] = make_float4(tv[0], tv[1], tv[2], tv[3]);
            }
        }
        #pragma unroll
        for (int r = 0; r < 4; r++) {
            int f = tid + r * 256;
            int krow = f >> 5, nq = f & 31;
            int kk2 = kt + krow;
            rb[r] = (kk2 < k1) ? *(const float4*)(F + (size_t)kk2 * d + ntile * 128 + nq * 4)
                               : make_float4(0.f, 0.f, 0.f, 0.f);
        }
    };

    // ---- split + STS of ra/rb into buffer `buf` ----
    auto do_fill = [&](int buf) {
        const uint32_t sAh = sbase + buf * STAGE;
        const uint32_t sAl = sAh + AP;
        const uint32_t sBh = sAl + AP;
        const uint32_t sBl = sBh + BP;
        #pragma unroll
        for (int r = 0; r < 4; r++) {
            int f = tid + r * 256;
            int m = f >> 3, q = f & 7;
            float v[4] = {ra[r].x * ESCALE, ra[r].y * ESCALE, ra[r].z * ESCALE, ra[r].w * ESCALE};
            uint32_t hi[2], lo[2];
            split4(v, hi, lo);
            uint32_t off = (uint32_t)(m * A_ROWB + q * 8);
            sts64(sAh + off, hi[0], hi[1]);
            sts64(sAl + off, lo[0], lo[1]);
        }
        #pragma unroll
        for (int r = 0; r < 4; r++) {
            int f = tid + r * 256;
            int krow = f >> 5, nq = f & 31;
            float v[4] = {rb[r].x, rb[r].y, rb[r].z, rb[r].w};
            uint32_t hi[2], lo[2];
            split4(v, hi, lo);
            uint32_t off = (uint32_t)(krow * B_ROWB + nq * 8);
            sts64(sBh + off, hi[0], hi[1]);
            sts64(sBl + off, lo[0], lo[1]);
        }
    };

    // ---- one k16 chunk of MMAs from buffer `buf` ----
    auto do_compute = [&](int buf, int kc) {
        const uint32_t sAh = sbase + buf * STAGE;
        const uint32_t sAl = sAh + AP;
        const uint32_t sBh = sAl + AP;
        const uint32_t sBl = sBh + BP;
        uint32_t ah[2][4], al[2][4];
        #pragma unroll
        for (int mt = 0; mt < 2; mt++) {
            uint32_t aoff = a_lane + (uint32_t)(mt * 16 * A_ROWB) + (uint32_t)(kc * 32);
            ldsm_x4(sAh + aoff, ah[mt][0], ah[mt][1], ah[mt][2], ah[mt][3]);
            ldsm_x4(sAl + aoff, al[mt][0], al[mt][1], al[mt][2], al[mt][3]);
        }
        const uint32_t bk = b_lane + (uint32_t)(kc * 16 * B_ROWB);
        #pragma unroll
        for (int jp = 0; jp < 4; jp++) {
            uint32_t bh[4], bl[4];
            uint32_t boff = bk + (uint32_t)(jp * 32);
            ldsm_x4t(sBh + boff, bh[0], bh[1], bh[2], bh[3]);
            ldsm_x4t(sBl + boff, bl[0], bl[1], bl[2], bl[3]);
            #pragma unroll
            for (int je = 0; je < 2; je++) {
                const int j = 2 * jp + je;
                uint32_t b0h = bh[2 * je], b1h = bh[2 * je + 1];
                uint32_t b0l = bl[2 * je], b1l = bl[2 * je + 1];
                mma_f16(acc[0][j], ah[0][0], ah[0][1], ah[0][2], ah[0][3], b0h, b1h);
                mma_f16(acc[0][j], al[0][0], al[0][1], al[0][2], al[0][3], b0h, b1h);
                mma_f16(acc[0][j], ah[0][0], ah[0][1], ah[0][2], ah[0][3], b0l, b1l);
                mma_f16(acc[1][j], ah[1][0], ah[1][1], ah[1][2], ah[1][3], b0h, b1h);
                mma_f16(acc[1][j], al[1][0], al[1][1], al[1][2], al[1][3], b0h, b1h);
                mma_f16(acc[1][j], ah[1][0], ah[1][1], ah[1][2], ah[1][3], b0l, b1l);
            }
        }
    };

    // ---- prologue: stage 0 into buffer 0 ----
    do_ldg(k0);
    do_fill(0);
    __syncthreads();

    // ---- mainloop: one barrier per stage, phase-staggered fill ----
    for (int t = 0; t < nstages; t++) {
        const int cur = t & 1;
        const int nxt = cur ^ 1;
        const bool hn = (t + 1 < nstages);

        if (hn) do_ldg(k0 + (t + 1) * KB);

        if (evenw) {
            do_compute(cur, 0);
            if (hn) do_fill(nxt);
            do_compute(cur, 1);
        } else {
            do_compute(cur, 0);
            do_compute(cur, 1);
            if (hn) do_fill(nxt);
        }
        __syncthreads();
    }

    // ---- epilogue: write split-K partial tile (undo ESCALE) ----
    float* P = g_partial + (size_t)(z * NSPLIT + s) * kd;
    const int rsub = l >> 2;
    const int csub = (l & 3) * 2;
    #pragma unroll
    for (int mt = 0; mt < 2; mt++) {
        #pragma unroll
        for (int j = 0; j < 8; j++) {
            int row = mbase + mt * 16 + rsub;
            int col = ntile * 128 + warpN * 64 + j * 8 + csub;
            *(float2*)(P + (size_t)row * DDIM + col) =
                make_float2(acc[mt][j][0] * EINV, acc[mt][j][1] * EINV);
            *(float2*)(P + (size_t)(row + 8) * DDIM + col) =
                make_float2(acc[mt][j][2] * EINV, acc[mt][j][3] * EINV);
        }
    }
}

// ---------------------------------------------------------------------------
// Kernel 2: deterministic split-K reduction -> g_A, g_B
// ---------------------------------------------------------------------------
__global__ void reduce_partials(int kd)
{
    int idx = blockIdx.x * blockDim.x + threadIdx.x;
    if (idx >= 2 * kd) return;
    int z = idx / kd;
    int e = idx - z * kd;
    const float* P = g_partial + (size_t)z * NSPLIT * kd;
    float sum = 0.f;
    #pragma unroll 4
    for (int s = 0; s < NSPLIT; s++) sum += P[(size_t)s * kd + e];
    (z ? g_B : g_A)[e] = sum;
}

// ---------------------------------------------------------------------------
// Kernel 3: Gram matrices
// ---------------------------------------------------------------------------
__global__ __launch_bounds__(KDIM)
void gram_kernel(int k, int d)
{
    __shared__ float row[DDIM];
    const int i = blockIdx.x;
    const int z = blockIdx.y;
    const int j = threadIdx.x;
    const float* src = z ? g_B : g_A;
    for (int t = j; t < d; t += KDIM) row[t] = src[i * d + t];
    __syncthreads();
    const float* aj = g_A + j * d;
    float sum = 0.f;
    #pragma unroll 8
    for (int t = 0; t < d; t++) sum = fmaf(row[t], aj[t], sum);
    (z ? g_BAt : g_AAt)[i * k + j] = sum;
}

// ---------------------------------------------------------------------------
// Kernel 4: one CTA per output row i. Blocked Cholesky (NB=16) + fwd/bwd subs.
// (R8 exact — 128 parallel CTAs, known 79 us.)
// ---------------------------------------------------------------------------
__global__ __launch_bounds__(512, 1)
void solve_kernel(const float* __restrict__ evx, const float* __restrict__ evy,
                  float* __restrict__ out)
{
    __shared__ float P[KDIM * (KDIM + 1) / 2];
    __shared__ float colb[NB][KDIM];
    __shared__ float yv[KDIM];
    __shared__ float invD[KDIM];

    const int i   = blockIdx.x;
    const int tid = threadIdx.x;
    const int t   = tid & 127;
    const int q   = tid >> 7;
    const int trit = t * (t + 1) / 2;

    for (int r0 = 0; r0 < KDIM; r0 += 4) {
        int r = r0 + q;
        if (t <= r) P[r * (r + 1) / 2 + t] = g_AAt[r * KDIM + t];
    }
    if (tid < KDIM) yv[tid] = g_BAt[i * KDIM + tid];
    __syncthreads();

    if (tid < KDIM) {
        float ev = evx[tid] - evy[i];
        P[trit + tid] += LAMBDA * ev * ev;
    }
    __syncthreads();

    for (int b = 0; b < KDIM / NB; b++) {
        const int j0  = b * NB;
        const int rlo = j0 + NB;

        if (tid < 32) {
            int lrow = tid & 15;
            int row = j0 + lrow;
            int trow = row * (row + 1) / 2;
            float dreg[NB];
            float myinv = 0.f;
            #pragma unroll
            for (int c = 0; c < NB; c++)
                dreg[c] = (c <= lrow) ? P[trow + j0 + c] : 0.f;

            #pragma unroll
            for (int c = 0; c < NB; c++) {
                float dc = __shfl_sync(0xffffffffu, dreg[c], c);
                float r  = rsqrtf(dc);
                if (lrow == c)      { dreg[c] = dc * r; myinv = r; }
                else if (lrow > c)  dreg[c] *= r;
                #pragma unroll
                for (int m = c + 1; m < NB; m++) {
                    float Lmc = __shfl_sync(0xffffffffu, dreg[c], m);
                    if (lrow >= m) dreg[m] -= dreg[c] * Lmc;
                }
            }
            if (tid < 16) {
                #pragma unroll
                for (int c = 0; c < NB; c++)
                    if (c <= lrow) P[trow + j0 + c] = dreg[c];
                invD[row] = myinv;
            }
        }
        __syncthreads();

        if (rlo >= KDIM) break;

        {
            int r = rlo + tid;
            if (r < KDIM) {
                int trr = r * (r + 1) / 2;
                float a[NB];
                #pragma unroll
                for (int j = 0; j < NB; j++) a[j] = P[trr + j0 + j];
                #pragma unroll
                for (int j = 0; j < NB; j++) {
                    float v = a[j];
                    int trj = (j0 + j) * (j0 + j + 1) / 2;
                    #pragma unroll
                    for (int c = 0; c < j; c++)
                        v -= a[c] * P[trj + j0 + c];
                    a[j] = v * invD[j0 + j];
                }
                #pragma unroll
                for (int j = 0; j < NB; j++) {
                    P[trr + j0 + j] = a[j];
                    colb[j][r] = a[j];
                }
            }
        }
        __syncthreads();

        if (t >= rlo) {
            float ar[NB];
            #pragma unroll
            for (int j = 0; j < NB; j++) ar[j] = colb[j][t];
            for (int c = rlo + q; c <= t; c += 4) {
                float a2 = P[trit + c];
                #pragma unroll
                for (int j = 0; j < NB; j++) a2 -= ar[j] * colb[j][c];
                P[trit + c] = a2;
            }
        }
        __syncthreads();
    }

    for (int b = 0; b < KDIM / NB; b++) {
        const int j0 = b * NB;
        if (tid < 32) {
            int lrow = tid & 15;
            int row = j0 + lrow;
            int trow = row * (row + 1) / 2;
            float yl = yv[row];
            #pragma unroll
            for (int c = 0; c < NB; c++) {
                int rc = j0 + c;
                float t2 = yl * invD[rc];
                yl = (lrow == c) ? t2 : yl;
                float yc = __shfl_sync(0xffffffffu, yl, c);
                if (lrow > c) yl -= P[trow + rc] * yc;
            }
            if (tid < 16) yv[row] = yl;
        }
        __syncthreads();
        {
            int r = j0 + NB + tid;
            if (r < KDIM) {
                int trr = r * (r + 1) / 2;
                float a2 = yv[r];
                #pragma unroll
                for (int c = 0; c < NB; c++)
                    a2 -= P[trr + j0 + c] * yv[j0 + c];
                yv[r] = a2;
            }
        }
        __syncthreads();
    }

    for (int b = KDIM / NB - 1; b >= 0; b--) {
        const int j0 = b * NB;
        if (tid < 32) {
            int lrow = tid & 15;
            int row = j0 + lrow;
            float xl = yv[row];
            #pragma unroll
            for (int c = NB - 1; c >= 0; c--) {
                int rc = j0 + c;
                int trc = rc * (rc + 1) / 2;
                float t2 = xl * invD[rc];
                xl = (lrow == c) ? t2 : xl;
                float xc = __shfl_sync(0xffffffffu, xl, c);
                if (lrow < c) xl -= P[trc + row] * xc;
            }
            if (tid < 16) yv[row] = xl;
        }
        __syncthreads();
        {
            int r = tid;
            if (r < j0) {
                float a2 = yv[r];
                #pragma unroll
                for (int c = 0; c < NB; c++) {
                    int rc = j0 + c;
                    a2 -= P[rc * (rc + 1) / 2 + r] * yv[rc];
                }
                yv[r] = a2;
            }
        }
        __syncthreads();
    }

    if (tid < KDIM) out[i * KDIM + tid] = yv[tid];
}

// ---------------------------------------------------------------------------
// Launch
// ---------------------------------------------------------------------------
extern "C" void kernel_launch(void* const* d_in, const int* in_sizes, int n_in,
                              void* d_out, int out_size)
{
    const float* feat_x = (const float*)d_in[0];
    const float* feat_y = (const float*)d_in[1];
    const float* evals_x = (const float*)d_in[2];
    const float* evals_y = (const float*)d_in[3];
    const float* Ex = (const float*)d_in[4];
    const float* Ey = (const float*)d_in[5];

    const int  k  = in_sizes[2];                  // 128
    const long N  = (long)in_sizes[4] / k;        // 200000
    const int  d  = (int)((long)in_sizes[0] / N); // 256
    const int  kd = k * d;

    int Kc = (int)((N + NSPLIT - 1) / NSPLIT);
    Kc = ((Kc + KB - 1) / KB) * KB;

    cudaFuncSetAttribute(gemm_mma, cudaFuncAttributeMaxDynamicSharedMemorySize, SMEM_GEMM);

    dim3 ggrid(2, NSPLIT, 2);
    gemm_mma<<<ggrid, 256, SMEM_GEMM>>>(Ex, feat_x, Ey, feat_y, (int)N, d, Kc, kd);

    reduce_partials<<<(2 * kd + 255) / 256, 256>>>(kd);

    gram_kernel<<<dim3(k, 2), KDIM>>>(k, d);

    solve_kernel<<<k, 512>>>(evals_x, evals_y, (float*)d_out);
}

// round 12
// speedup vs baseline: 1.0905x; 1.0311x over previous
#include <cuda_runtime.h>
#include <cuda_fp16.h>
#include <cstdint>
#include <math.h>

// Problem constants (dataset-fixed shapes)
#define LAMBDA   1e-3f
#define KDIM     128      // k
#define DDIM     256      // d
#define NSPLIT   37       // split-K chunks (2 ntiles * 37 * 2 tensors = 148 CTAs = 1 wave)
#define KB       32       // K per mainloop stage (2 x k16 chunks)
#define NB       16       // Cholesky block size
#define ESCALE   512.0f   // power-of-2 scale so E's lo-halves stay in fp16 normal range
#define EINV     (1.0f / 512.0f)

// Scratch (device globals only)
__device__ float g_partial[2 * NSPLIT * KDIM * DDIM];   // ~9.7 MB split-K partials
__device__ float g_A[KDIM * DDIM];
__device__ float g_B[KDIM * DDIM];
__device__ float g_AAt[KDIM * KDIM];
__device__ float g_BAt[KDIM * KDIM];

// ---------------------------------------------------------------------------
// helpers
// ---------------------------------------------------------------------------
__device__ __forceinline__ uint32_t smem_u32(const void* p) {
    uint32_t a;
    asm("{ .reg .u64 t; cvta.to.shared.u64 t, %1; cvt.u32.u64 %0, t; }" : "=r"(a) : "l"(p));
    return a;
}
__device__ __forceinline__ void sts64(uint32_t a, uint32_t x, uint32_t y) {
    asm volatile("st.shared.v2.b32 [%0], {%1,%2};" :: "r"(a), "r"(x), "r"(y) : "memory");
}
__device__ __forceinline__ void ldsm_x4(uint32_t addr, uint32_t& r0, uint32_t& r1, uint32_t& r2, uint32_t& r3) {
    asm volatile("ldmatrix.sync.aligned.m8n8.x4.shared.b16 {%0,%1,%2,%3}, [%4];"
                 : "=r"(r0), "=r"(r1), "=r"(r2), "=r"(r3) : "r"(addr));
}
__device__ __forceinline__ void ldsm_x4t(uint32_t addr, uint32_t& r0, uint32_t& r1, uint32_t& r2, uint32_t& r3) {
    asm volatile("ldmatrix.sync.aligned.m8n8.x4.trans.shared.b16 {%0,%1,%2,%3}, [%4];"
                 : "=r"(r0), "=r"(r1), "=r"(r2), "=r"(r3) : "r"(addr));
}
// fp16 mma: D(16x8) += A(16x16) * B(16x8), fp32 accum
__device__ __forceinline__ void mma_f16(float* c,
                                        uint32_t a0, uint32_t a1, uint32_t a2, uint32_t a3,
                                        uint32_t b0, uint32_t b1) {
    asm volatile(
        "mma.sync.aligned.m16n8k16.row.col.f32.f16.f16.f32 "
        "{%0,%1,%2,%3}, {%4,%5,%6,%7}, {%8,%9}, {%0,%1,%2,%3};"
        : "+f"(c[0]), "+f"(c[1]), "+f"(c[2]), "+f"(c[3])
        : "r"(a0), "r"(a1), "r"(a2), "r"(a3), "r"(b0), "r"(b1));
}
// split x (4 floats) into hi/lo half2 pairs (packed uint32)
__device__ __forceinline__ void split4(const float* v, uint32_t* hi, uint32_t* lo) {
    __half2 h0 = __floats2half2_rn(v[0], v[1]);
    __half2 h1 = __floats2half2_rn(v[2], v[3]);
    float2 f0 = __half22float2(h0);
    float2 f1 = __half22float2(h1);
    __half2 l0 = __floats2half2_rn(v[0] - f0.x, v[1] - f0.y);
    __half2 l1 = __floats2half2_rn(v[2] - f1.x, v[3] - f1.y);
    hi[0] = *(uint32_t*)&h0; hi[1] = *(uint32_t*)&h1;
    lo[0] = *(uint32_t*)&l0; lo[1] = *(uint32_t*)&l1;
}

// ---------------------------------------------------------------------------
// GEMM SMEM layout per stage (conflict-free bank rotations, R8 config)
// ---------------------------------------------------------------------------
#define A_ROWB   80
#define AP       (128 * A_ROWB)              // 10240 per plane
#define B_ROWB   272
#define BP       (32 * B_ROWB)               // 8704 per plane
#define STAGE    (2 * AP + 2 * BP)           // 37888
#define SMEM_GEMM (2 * STAGE)                // 75776

// ---------------------------------------------------------------------------
// Kernel 1: 3xFP16 (Markidis split) mma.sync split-K GEMM (R8 exact, frozen).
// ---------------------------------------------------------------------------
__global__ __launch_bounds__(256, 1)
void gemm_mma(const float* __restrict__ Ex, const float* __restrict__ Fx,
              const float* __restrict__ Ey, const float* __restrict__ Fy,
              int N, int d, int Kc, int kd)
{
    extern __shared__ char smem[];
    const uint32_t sbase = smem_u32(smem);

    const int ntile = blockIdx.x;
    const int s     = blockIdx.y;
    const int z     = blockIdx.z;
    const float* __restrict__ E = z ? Ey : Ex;
    const float* __restrict__ F = z ? Fy : Fx;

    const int k0 = s * Kc;
    const int k1 = min(k0 + Kc, N);
    const int nstages = (k1 - k0 + KB - 1) / KB;

    const int tid  = threadIdx.x;
    const int l    = tid & 31;
    const int wid  = tid >> 5;
    const int warpM = wid & 3;
    const int warpN = wid >> 2;
    const int mbase = warpM * 32;

    const uint32_t a_lane = (uint32_t)((l & 15) * A_ROWB + ((l >> 4) << 4)) + (uint32_t)(mbase * A_ROWB);
    const uint32_t b_lane = (uint32_t)((l & 15) * B_ROWB + ((l >> 4) << 4)) + (uint32_t)(warpN * 64 * 2);

    float acc[2][8][4];
    #pragma unroll
    for (int a = 0; a < 2; a++)
        #pragma unroll
        for (int b = 0; b < 8; b++)
            #pragma unroll
            for (int c = 0; c < 4; c++) acc[a][b][c] = 0.f;

    float4 ra[4], rb[4];

    {
        const int kt = k0;
        const bool full = (kt + KB) <= k1;
        #pragma unroll
        for (int r = 0; r < 4; r++) {
            int f = tid + r * 256;
            int m = f >> 3, q = f & 7;
            if (full) {
                ra[r] = *(const float4*)(E + (size_t)m * N + kt + q * 4);
            } else {
                float tv[4];
                #pragma unroll
                for (int jj = 0; jj < 4; jj++) {
                    int kk2 = kt + q * 4 + jj;
                    tv[jj] = (kk2 < k1) ? E[(size_t)m * N + kk2] : 0.f;
                }
                ra[r] = make_float4(tv[0], tv[1], tv[2], tv[3]);
            }
        }
        #pragma unroll
        for (int r = 0; r < 4; r++) {
            int f = tid + r * 256;
            int krow = f >> 5, nq = f & 31;
            int kk2 = kt + krow;
            rb[r] = (kk2 < k1) ? *(const float4*)(F + (size_t)kk2 * d + ntile * 128 + nq * 4)
                               : make_float4(0.f, 0.f, 0.f, 0.f);
        }
    }

    for (int t = 0; t < nstages; t++) {
        const uint32_t sAh = sbase + (t & 1) * STAGE;
        const uint32_t sAl = sAh + AP;
        const uint32_t sBh = sAl + AP;
        const uint32_t sBl = sBh + BP;

        #pragma unroll
        for (int r = 0; r < 4; r++) {
            int f = tid + r * 256;
            int m = f >> 3, q = f & 7;
            float v[4] = {ra[r].x * ESCALE, ra[r].y * ESCALE, ra[r].z * ESCALE, ra[r].w * ESCALE};
            uint32_t hi[2], lo[2];
            split4(v, hi, lo);
            uint32_t off = (uint32_t)(m * A_ROWB + q * 8);
            sts64(sAh + off, hi[0], hi[1]);
            sts64(sAl + off, lo[0], lo[1]);
        }
        #pragma unroll
        for (int r = 0; r < 4; r++) {
            int f = tid + r * 256;
            int krow = f >> 5, nq = f & 31;
            float v[4] = {rb[r].x, rb[r].y, rb[r].z, rb[r].w};
            uint32_t hi[2], lo[2];
            split4(v, hi, lo);
            uint32_t off = (uint32_t)(krow * B_ROWB + nq * 8);
            sts64(sBh + off, hi[0], hi[1]);
            sts64(sBl + off, lo[0], lo[1]);
        }
        __syncthreads();

        if (t + 1 < nstages) {
            const int kt = k0 + (t + 1) * KB;
            const bool full = (kt + KB) <= k1;
            #pragma unroll
            for (int r = 0; r < 4; r++) {
                int f = tid + r * 256;
                int m = f >> 3, q = f & 7;
                if (full) {
                    ra[r] = *(const float4*)(E + (size_t)m * N + kt + q * 4);
                } else {
                    float tv[4];
                    #pragma unroll
                    for (int jj = 0; jj < 4; jj++) {
                        int kk2 = kt + q * 4 + jj;
                        tv[jj] = (kk2 < k1) ? E[(size_t)m * N + kk2] : 0.f;
                    }
                    ra[r] = make_float4(tv[0], tv[1], tv[2], tv[3]);
                }
            }
            #pragma unroll
            for (int r = 0; r < 4; r++) {
                int f = tid + r * 256;
                int krow = f >> 5, nq = f & 31;
                int kk2 = kt + krow;
                rb[r] = (kk2 < k1) ? *(const float4*)(F + (size_t)kk2 * d + ntile * 128 + nq * 4)
                                   : make_float4(0.f, 0.f, 0.f, 0.f);
            }
        }

        #pragma unroll
        for (int kc = 0; kc < 2; kc++) {
            uint32_t ah[2][4], al[2][4];
            #pragma unroll
            for (int mt = 0; mt < 2; mt++) {
                uint32_t aoff = a_lane + (uint32_t)(mt * 16 * A_ROWB) + (uint32_t)(kc * 32);
                ldsm_x4(sAh + aoff, ah[mt][0], ah[mt][1], ah[mt][2], ah[mt][3]);
                ldsm_x4(sAl + aoff, al[mt][0], al[mt][1], al[mt][2], al[mt][3]);
            }
            const uint32_t bk = b_lane + (uint32_t)(kc * 16 * B_ROWB);
            #pragma unroll
            for (int jp = 0; jp < 4; jp++) {
                uint32_t bh[4], bl[4];
                uint32_t boff = bk + (uint32_t)(jp * 32);
                ldsm_x4t(sBh + boff, bh[0], bh[1], bh[2], bh[3]);
                ldsm_x4t(sBl + boff, bl[0], bl[1], bl[2], bl[3]);
                #pragma unroll
                for (int je = 0; je < 2; je++) {
                    const int j = 2 * jp + je;
                    uint32_t b0h = bh[2 * je], b1h = bh[2 * je + 1];
                    uint32_t b0l = bl[2 * je], b1l = bl[2 * je + 1];
                    mma_f16(acc[0][j], ah[0][0], ah[0][1], ah[0][2], ah[0][3], b0h, b1h);
                    mma_f16(acc[0][j], al[0][0], al[0][1], al[0][2], al[0][3], b0h, b1h);
                    mma_f16(acc[0][j], ah[0][0], ah[0][1], ah[0][2], ah[0][3], b0l, b1l);
                    mma_f16(acc[1][j], ah[1][0], ah[1][1], ah[1][2], ah[1][3], b0h, b1h);
                    mma_f16(acc[1][j], al[1][0], al[1][1], al[1][2], al[1][3], b0h, b1h);
                    mma_f16(acc[1][j], ah[1][0], ah[1][1], ah[1][2], ah[1][3], b0l, b1l);
                }
            }
        }
        __syncthreads();
    }

    float* P = g_partial + (size_t)(z * NSPLIT + s) * kd;
    const int rsub = l >> 2;
    const int csub = (l & 3) * 2;
    #pragma unroll
    for (int mt = 0; mt < 2; mt++) {
        #pragma unroll
        for (int j = 0; j < 8; j++) {
            int row = mbase + mt * 16 + rsub;
            int col = ntile * 128 + warpN * 64 + j * 8 + csub;
            *(float2*)(P + (size_t)row * DDIM + col) =
                make_float2(acc[mt][j][0] * EINV, acc[mt][j][1] * EINV);
            *(float2*)(P + (size_t)(row + 8) * DDIM + col) =
                make_float2(acc[mt][j][2] * EINV, acc[mt][j][3] * EINV);
        }
    }
}

// ---------------------------------------------------------------------------
// Kernel 2: deterministic split-K reduction -> g_A, g_B
// ---------------------------------------------------------------------------
__global__ void reduce_partials(int kd)
{
    int idx = blockIdx.x * blockDim.x + threadIdx.x;
    if (idx >= 2 * kd) return;
    int z = idx / kd;
    int e = idx - z * kd;
    const float* P = g_partial + (size_t)z * NSPLIT * kd;
    float sum = 0.f;
    #pragma unroll 4
    for (int s = 0; s < NSPLIT; s++) sum += P[(size_t)s * kd + e];
    (z ? g_B : g_A)[e] = sum;
}

// ---------------------------------------------------------------------------
// Kernel 3: Gram matrices
// ---------------------------------------------------------------------------
__global__ __launch_bounds__(KDIM)
void gram_kernel(int k, int d)
{
    __shared__ float row[DDIM];
    const int i = blockIdx.x;
    const int z = blockIdx.y;
    const int j = threadIdx.x;
    const float* src = z ? g_B : g_A;
    for (int t = j; t < d; t += KDIM) row[t] = src[i * d + t];
    __syncthreads();
    const float* aj = g_A + j * d;
    float sum = 0.f;
    #pragma unroll 8
    for (int t = 0; t < d; t++) sum = fmaf(row[t], aj[t], sum);
    (z ? g_BAt : g_AAt)[i * k + j] = sum;
}

// ---------------------------------------------------------------------------
// Kernel 4: TWO systems per CTA (grid 64 x 2 subsets of 256 threads, named
// barriers). The two serial Cholesky chains interleave on the SMSPs, hiding
// each other's shfl/LDS latency. Substitution chains preload L-columns and
// invD into registers so the dependent chain is shfl+FMA only.
// ---------------------------------------------------------------------------
#define TRI (KDIM * (KDIM + 1) / 2)
#define SOLVE_SMEM ((2 * TRI + 2 * NB * KDIM + 4 * KDIM) * 4)

__global__ __launch_bounds__(512, 1)
void solve_kernel(const float* __restrict__ evx, const float* __restrict__ evy,
                  float* __restrict__ out)
{
    extern __shared__ float dyn[];

    const int tid  = threadIdx.x;
    const int sys  = tid >> 8;         // 0 or 1
    const int stid = tid & 255;
    const int i    = blockIdx.x * 2 + sys;
    const int t    = stid & 127;
    const int q    = stid >> 7;        // 0..1
    const int trit = t * (t + 1) / 2;

    float* Pp   = dyn + sys * TRI;
    float* cb   = dyn + 2 * TRI + sys * (NB * KDIM);       // colb[j][r] = cb[j*KDIM + r]
    float* yv   = dyn + 2 * TRI + 2 * NB * KDIM + sys * KDIM;
    float* invD = dyn + 2 * TRI + 2 * NB * KDIM + 2 * KDIM + sys * KDIM;

#define BARS() asm volatile("bar.sync %0, 256;" :: "r"(sys + 1) : "memory")

    // ---- load lower triangle of AAt + rhs ----
    for (int r0 = 0; r0 < KDIM; r0 += 2) {
        int r = r0 + q;
        if (t <= r) Pp[r * (r + 1) / 2 + t] = g_AAt[r * KDIM + t];
    }
    if (stid < KDIM) {
        yv[stid] = g_BAt[i * KDIM + stid];
        float ev = evx[stid] - evy[i];
        BARS();     // triangle loaded before diagonal add (t==stid path below)
        Pp[trit + stid] += LAMBDA * ev * ev;
    } else {
        BARS();
    }
    BARS();

    // ================= blocked Cholesky =================
    for (int b = 0; b < KDIM / NB; b++) {
        const int j0  = b * NB;
        const int rlo = j0 + NB;

        if (stid < 32) {
            int lrow = stid & 15;
            int row = j0 + lrow;
            int trow = row * (row + 1) / 2;
            float dreg[NB];
            float myinv = 0.f;
            #pragma unroll
            for (int c = 0; c < NB; c++)
                dreg[c] = (c <= lrow) ? Pp[trow + j0 + c] : 0.f;

            #pragma unroll
            for (int c = 0; c < NB; c++) {
                float dc = __shfl_sync(0xffffffffu, dreg[c], c);
                float r  = rsqrtf(dc);
                if (lrow == c)      { dreg[c] = dc * r; myinv = r; }
                else if (lrow > c)  dreg[c] *= r;
                #pragma unroll
                for (int m = c + 1; m < NB; m++) {
                    float Lmc = __shfl_sync(0xffffffffu, dreg[c], m);
                    if (lrow >= m) dreg[m] -= dreg[c] * Lmc;
                }
            }
            if (stid < 16) {
                #pragma unroll
                for (int c = 0; c < NB; c++)
                    if (c <= lrow) Pp[trow + j0 + c] = dreg[c];
                invD[row] = myinv;
            }
        }
        BARS();

        if (rlo >= KDIM) break;

        // PANEL: rows rlo..127, thread-per-row
        {
            int r = rlo + stid;
            if (r < KDIM) {
                int trr = r * (r + 1) / 2;
                float a[NB];
                #pragma unroll
                for (int j = 0; j < NB; j++) a[j] = Pp[trr + j0 + j];
                #pragma unroll
                for (int j = 0; j < NB; j++) {
                    float v = a[j];
                    int trj = (j0 + j) * (j0 + j + 1) / 2;
                    #pragma unroll
                    for (int c = 0; c < j; c++)
                        v -= a[c] * Pp[trj + j0 + c];
                    a[j] = v * invD[j0 + j];
                }
                #pragma unroll
                for (int j = 0; j < NB; j++) {
                    Pp[trr + j0 + j] = a[j];
                    cb[j * KDIM + r] = a[j];
                }
            }
        }
        BARS();

        // SYRK: trailing update, 2-way column striping
        if (t >= rlo) {
            float ar[NB];
            #pragma unroll
            for (int j = 0; j < NB; j++) ar[j] = cb[j * KDIM + t];
            for (int c = rlo + q; c <= t; c += 2) {
                float a2 = Pp[trit + c];
                #pragma unroll
                for (int j = 0; j < NB; j++) a2 -= ar[j] * cb[j * KDIM + c];
                Pp[trit + c] = a2;
            }
        }
        BARS();
    }

    // ================= forward substitution: L y = b =================
    for (int b = 0; b < KDIM / NB; b++) {
        const int j0 = b * NB;
        if (stid < 32) {
            int lrow = stid & 15;
            int row = j0 + lrow;
            int trow = row * (row + 1) / 2;
            float lv[NB], idv[NB];
            #pragma unroll
            for (int c = 0; c < NB; c++) {
                lv[c]  = Pp[trow + j0 + c];    // only c < lrow used
                idv[c] = invD[j0 + c];
            }
            float yl = yv[row];
            #pragma unroll
            for (int c = 0; c < NB; c++) {
                float t2 = yl * idv[c];
                yl = (lrow == c) ? t2 : yl;
                float yc = __shfl_sync(0xffffffffu, yl, c);
                if (lrow > c) yl -= lv[c] * yc;
            }
            if (stid < 16) yv[row] = yl;
        }
        BARS();
        {
            int r = j0 + NB + stid;
            if (r < KDIM) {
                int trr = r * (r + 1) / 2;
                float a2 = yv[r];
                #pragma unroll
                for (int c = 0; c < NB; c++)
                    a2 -= Pp[trr + j0 + c] * yv[j0 + c];
                yv[r] = a2;
            }
        }
        BARS();
    }

    // ================= backward substitution: L^T x = y =================
    for (int b = KDIM / NB - 1; b >= 0; b--) {
        const int j0 = b * NB;
        if (stid < 32) {
            int lrow = stid & 15;
            int row = j0 + lrow;
            float lv[NB], idv[NB];
            #pragma unroll
            for (int c = 0; c < NB; c++) {
                int rc = j0 + c;
                lv[c]  = Pp[rc * (rc + 1) / 2 + row];   // only c > lrow used
                idv[c] = invD[rc];
            }
            float xl = yv[row];
            #pragma unroll
            for (int c = NB - 1; c >= 0; c--) {
                float t2 = xl * idv[c];
                xl = (lrow == c) ? t2 : xl;
                float xc = __shfl_sync(0xffffffffu, xl, c);
                if (lrow < c) xl -= lv[c] * xc;
            }
            if (stid < 16) yv[row] = xl;
        }
        BARS();
        {
            int r = stid;
            if (r < j0) {
                float a2 = yv[r];
                #pragma unroll
                for (int c = 0; c < NB; c++) {
                    int rc = j0 + c;
                    a2 -= Pp[rc * (rc + 1) / 2 + r] * yv[rc];
                }
                yv[r] = a2;
            }
        }
        BARS();
    }

    if (stid < KDIM) out[i * KDIM + stid] = yv[stid];
#undef BARS
}

// ---------------------------------------------------------------------------
// Launch
// ---------------------------------------------------------------------------
extern "C" void kernel_launch(void* const* d_in, const int* in_sizes, int n_in,
                              void* d_out, int out_size)
{
    const float* feat_x = (const float*)d_in[0];
    const float* feat_y = (const float*)d_in[1];
    const float* evals_x = (const float*)d_in[2];
    const float* evals_y = (const float*)d_in[3];
    const float* Ex = (const float*)d_in[4];
    const float* Ey = (const float*)d_in[5];

    const int  k  = in_sizes[2];                  // 128
    const long N  = (long)in_sizes[4] / k;        // 200000
    const int  d  = (int)((long)in_sizes[0] / N); // 256
    const int  kd = k * d;

    int Kc = (int)((N + NSPLIT - 1) / NSPLIT);
    Kc = ((Kc + KB - 1) / KB) * KB;

    cudaFuncSetAttribute(gemm_mma, cudaFuncAttributeMaxDynamicSharedMemorySize, SMEM_GEMM);
    cudaFuncSetAttribute(solve_kernel, cudaFuncAttributeMaxDynamicSharedMemorySize, SOLVE_SMEM);

    dim3 ggrid(2, NSPLIT, 2);
    gemm_mma<<<ggrid, 256, SMEM_GEMM>>>(Ex, feat_x, Ey, feat_y, (int)N, d, Kc, kd);

    reduce_partials<<<(2 * kd + 255) / 256, 256>>>(kd);

    gram_kernel<<<dim3(k, 2), KDIM>>>(k, d);

    solve_kernel<<<k / 2, 512, SOLVE_SMEM>>>(evals_x, evals_y, (float*)d_out);
}

// round 13
// speedup vs baseline: 1.1426x; 1.0477x over previous
#include <cuda_runtime.h>
#include <cuda_fp16.h>
#include <cstdint>
#include <math.h>

// Problem constants (dataset-fixed shapes)
#define LAMBDA   1e-3f
#define KDIM     128      // k
#define DDIM     256      // d
#define NSPLIT   37       // split-K chunks (2 ntiles * 37 * 2 tensors = 148 CTAs = 1 wave)
#define KB       32       // K per mainloop stage (2 x k16 chunks)
#define NB       16       // Cholesky block size
#define ESCALE   512.0f
#define EINV     (1.0f / 512.0f)

#define NTHREADS 384      // 8 consumer warps + 4 producer warps
#define BARCNT   384

// Scratch (device globals only)
__device__ float g_partial[2 * NSPLIT * KDIM * DDIM];
__device__ float g_A[KDIM * DDIM];
__device__ float g_B[KDIM * DDIM];
__device__ float g_AAt[KDIM * KDIM];
__device__ float g_BAt[KDIM * KDIM];

// ---------------------------------------------------------------------------
// helpers
// ---------------------------------------------------------------------------
__device__ __forceinline__ uint32_t smem_u32(const void* p) {
    uint32_t a;
    asm("{ .reg .u64 t; cvta.to.shared.u64 t, %1; cvt.u32.u64 %0, t; }" : "=r"(a) : "l"(p));
    return a;
}
__device__ __forceinline__ void sts64(uint32_t a, uint32_t x, uint32_t y) {
    asm volatile("st.shared.v2.b32 [%0], {%1,%2};" :: "r"(a), "r"(x), "r"(y) : "memory");
}
__device__ __forceinline__ void ldsm_x4(uint32_t addr, uint32_t& r0, uint32_t& r1, uint32_t& r2, uint32_t& r3) {
    asm volatile("ldmatrix.sync.aligned.m8n8.x4.shared.b16 {%0,%1,%2,%3}, [%4];"
                 : "=r"(r0), "=r"(r1), "=r"(r2), "=r"(r3) : "r"(addr));
}
__device__ __forceinline__ void ldsm_x4t(uint32_t addr, uint32_t& r0, uint32_t& r1, uint32_t& r2, uint32_t& r3) {
    asm volatile("ldmatrix.sync.aligned.m8n8.x4.trans.shared.b16 {%0,%1,%2,%3}, [%4];"
                 : "=r"(r0), "=r"(r1), "=r"(r2), "=r"(r3) : "r"(addr));
}
__device__ __forceinline__ void mma_f16(float* c,
                                        uint32_t a0, uint32_t a1, uint32_t a2, uint32_t a3,
                                        uint32_t b0, uint32_t b1) {
    asm volatile(
        "mma.sync.aligned.m16n8k16.row.col.f32.f16.f16.f32 "
        "{%0,%1,%2,%3}, {%4,%5,%6,%7}, {%8,%9}, {%0,%1,%2,%3};"
        : "+f"(c[0]), "+f"(c[1]), "+f"(c[2]), "+f"(c[3])
        : "r"(a0), "r"(a1), "r"(a2), "r"(a3), "r"(b0), "r"(b1));
}
__device__ __forceinline__ void split4(const float* v, uint32_t* hi, uint32_t* lo) {
    __half2 h0 = __floats2half2_rn(v[0], v[1]);
    __half2 h1 = __floats2half2_rn(v[2], v[3]);
    float2 f0 = __half22float2(h0);
    float2 f1 = __half22float2(h1);
    __half2 l0 = __floats2half2_rn(v[0] - f0.x, v[1] - f0.y);
    __half2 l1 = __floats2half2_rn(v[2] - f1.x, v[3] - f1.y);
    hi[0] = *(uint32_t*)&h0; hi[1] = *(uint32_t*)&h1;
    lo[0] = *(uint32_t*)&l0; lo[1] = *(uint32_t*)&l1;
}
#define BAR_SYNC(id)   asm volatile("bar.sync %0, %1;"   :: "r"(id), "r"(BARCNT) : "memory")
#define BAR_ARRIVE(id) asm volatile("bar.arrive %0, %1;" :: "r"(id), "r"(BARCNT) : "memory")

// ---------------------------------------------------------------------------
// GEMM SMEM layout per stage (conflict-free, R8 config)
// ---------------------------------------------------------------------------
#define A_ROWB   80
#define AP       (128 * A_ROWB)
#define B_ROWB   272
#define BP       (32 * B_ROWB)
#define STAGE    (2 * AP + 2 * BP)           // 37888
#define SMEM_GEMM (2 * STAGE)                // 75776

// ---------------------------------------------------------------------------
// Kernel 1: warp-specialized 3xFP16 split-K GEMM.
//   warps 0-7: consumers (ldsm + MMA only, R8 accumulator layout)
//   warps 8-11: producers (LDG + fp16 hi/lo split + STS)
//   named barriers: full[buf]=1+buf, free[buf]=3+buf, count=384
// ---------------------------------------------------------------------------
__global__ __launch_bounds__(NTHREADS, 1)
void gemm_mma(const float* __restrict__ Ex, const float* __restrict__ Fx,
              const float* __restrict__ Ey, const float* __restrict__ Fy,
              int N, int d, int Kc, int kd)
{
    extern __shared__ char smem[];
    const uint32_t sbase = smem_u32(smem);

    const int ntile = blockIdx.x;
    const int s     = blockIdx.y;
    const int z     = blockIdx.z;
    const float* __restrict__ E = z ? Ey : Ex;
    const float* __restrict__ F = z ? Fy : Fx;

    const int k0 = s * Kc;
    const int k1 = min(k0 + Kc, N);
    const int nstages = (k1 - k0 + KB - 1) / KB;

    const int tid = threadIdx.x;
    const int l   = tid & 31;
    const int wid = tid >> 5;

    if (wid >= 8) {
        // ==================== PRODUCER ====================
        const int p = tid - 256;              // 0..127
        const int am = p >> 3;                // A row group base (+16r)
        const int aq = p & 7;                 // A float4 col
        const int bk = p >> 5;                // B k-row base (+4r)
        const int bn = p & 31;                // B float4 col

        float4 ra[8], rb[8];
        for (int t = 0; t < nstages; t++) {
            const int kt = k0 + t * KB;
            const bool full = (kt + KB) <= k1;

            // LDG stage t (16 float4, MLP-heavy)
            #pragma unroll
            for (int r = 0; r < 8; r++) {
                int m = am + 16 * r;
                if (full) {
                    ra[r] = *(const float4*)(E + (size_t)m * N + kt + aq * 4);
                } else {
                    float tv[4];
                    #pragma unroll
                    for (int jj = 0; jj < 4; jj++) {
                        int kk2 = kt + aq * 4 + jj;
                        tv[jj] = (kk2 < k1) ? E[(size_t)m * N + kk2] : 0.f;
                    }
                    ra[r] = make_float4(tv[0], tv[1], tv[2], tv[3]);
                }
            }
            #pragma unroll
            for (int r = 0; r < 8; r++) {
                int krow = bk + 4 * r;
                int kk2 = kt + krow;
                rb[r] = (kk2 < k1) ? *(const float4*)(F + (size_t)kk2 * d + ntile * 128 + bn * 4)
                                   : make_float4(0.f, 0.f, 0.f, 0.f);
            }

            const int buf = t & 1;
            if (t >= 2) BAR_SYNC(3 + buf);    // wait consumers done with this buffer

            const uint32_t sAh = sbase + buf * STAGE;
            const uint32_t sAl = sAh + AP;
            const uint32_t sBh = sAl + AP;
            const uint32_t sBl = sBh + BP;

            #pragma unroll
            for (int r = 0; r < 8; r++) {
                int m = am + 16 * r;
                float v[4] = {ra[r].x * ESCALE, ra[r].y * ESCALE, ra[r].z * ESCALE, ra[r].w * ESCALE};
                uint32_t hi[2], lo[2];
                split4(v, hi, lo);
                uint32_t off = (uint32_t)(m * A_ROWB + aq * 8);
                sts64(sAh + off, hi[0], hi[1]);
                sts64(sAl + off, lo[0], lo[1]);
            }
            #pragma unroll
            for (int r = 0; r < 8; r++) {
                int krow = bk + 4 * r;
                float v[4] = {rb[r].x, rb[r].y, rb[r].z, rb[r].w};
                uint32_t hi[2], lo[2];
                split4(v, hi, lo);
                uint32_t off = (uint32_t)(krow * B_ROWB + bn * 8);
                sts64(sBh + off, hi[0], hi[1]);
                sts64(sBl + off, lo[0], lo[1]);
            }
            BAR_ARRIVE(1 + buf);              // buffer full
        }
        return;
    }

    // ==================== CONSUMER ====================
    const int warpM = wid & 3;
    const int warpN = wid >> 2;
    const int mbase = warpM * 32;

    const uint32_t a_lane = (uint32_t)((l & 15) * A_ROWB + ((l >> 4) << 4)) + (uint32_t)(mbase * A_ROWB);
    const uint32_t b_lane = (uint32_t)((l & 15) * B_ROWB + ((l >> 4) << 4)) + (uint32_t)(warpN * 64 * 2);

    float acc[2][8][4];
    #pragma unroll
    for (int a = 0; a < 2; a++)
        #pragma unroll
        for (int b = 0; b < 8; b++)
            #pragma unroll
            for (int c = 0; c < 4; c++) acc[a][b][c] = 0.f;

    for (int t = 0; t < nstages; t++) {
        const int buf = t & 1;
        BAR_SYNC(1 + buf);                    // wait buffer full

        const uint32_t sAh = sbase + buf * STAGE;
        const uint32_t sAl = sAh + AP;
        const uint32_t sBh = sAl + AP;
        const uint32_t sBl = sBh + BP;

        #pragma unroll
        for (int kc = 0; kc < 2; kc++) {
            uint32_t ah[2][4], al[2][4];
            #pragma unroll
            for (int mt = 0; mt < 2; mt++) {
                uint32_t aoff = a_lane + (uint32_t)(mt * 16 * A_ROWB) + (uint32_t)(kc * 32);
                ldsm_x4(sAh + aoff, ah[mt][0], ah[mt][1], ah[mt][2], ah[mt][3]);
                ldsm_x4(sAl + aoff, al[mt][0], al[mt][1], al[mt][2], al[mt][3]);
            }
            const uint32_t bkoff = b_lane + (uint32_t)(kc * 16 * B_ROWB);
            #pragma unroll
            for (int jp = 0; jp < 4; jp++) {
                uint32_t bh[4], bl[4];
                uint32_t boff = bkoff + (uint32_t)(jp * 32);
                ldsm_x4t(sBh + boff, bh[0], bh[1], bh[2], bh[3]);
                ldsm_x4t(sBl + boff, bl[0], bl[1], bl[2], bl[3]);
                #pragma unroll
                for (int je = 0; je < 2; je++) {
                    const int j = 2 * jp + je;
                    uint32_t b0h = bh[2 * je], b1h = bh[2 * je + 1];
                    uint32_t b0l = bl[2 * je], b1l = bl[2 * je + 1];
                    mma_f16(acc[0][j], ah[0][0], ah[0][1], ah[0][2], ah[0][3], b0h, b1h);
                    mma_f16(acc[0][j], al[0][0], al[0][1], al[0][2], al[0][3], b0h, b1h);
                    mma_f16(acc[0][j], ah[0][0], ah[0][1], ah[0][2], ah[0][3], b0l, b1l);
                    mma_f16(acc[1][j], ah[1][0], ah[1][1], ah[1][2], ah[1][3], b0h, b1h);
                    mma_f16(acc[1][j], al[1][0], al[1][1], al[1][2], al[1][3], b0h, b1h);
                    mma_f16(acc[1][j], ah[1][0], ah[1][1], ah[1][2], ah[1][3], b0l, b1l);
                }
            }
        }
        BAR_ARRIVE(3 + buf);                  // buffer free
    }

    // ---- epilogue: write split-K partial tile (undo ESCALE) ----
    float* P = g_partial + (size_t)(z * NSPLIT + s) * kd;
    const int rsub = l >> 2;
    const int csub = (l & 3) * 2;
    #pragma unroll
    for (int mt = 0; mt < 2; mt++) {
        #pragma unroll
        for (int j = 0; j < 8; j++) {
            int row = mbase + mt * 16 + rsub;
            int col = ntile * 128 + warpN * 64 + j * 8 + csub;
            *(float2*)(P + (size_t)row * DDIM + col) =
                make_float2(acc[mt][j][0] * EINV, acc[mt][j][1] * EINV);
            *(float2*)(P + (size_t)(row + 8) * DDIM + col) =
                make_float2(acc[mt][j][2] * EINV, acc[mt][j][3] * EINV);
        }
    }
}

// ---------------------------------------------------------------------------
// Kernel 2: deterministic split-K reduction -> g_A, g_B
// ---------------------------------------------------------------------------
__global__ void reduce_partials(int kd)
{
    int idx = blockIdx.x * blockDim.x + threadIdx.x;
    if (idx >= 2 * kd) return;
    int z = idx / kd;
    int e = idx - z * kd;
    const float* P = g_partial + (size_t)z * NSPLIT * kd;
    float sum = 0.f;
    #pragma unroll 4
    for (int s = 0; s < NSPLIT; s++) sum += P[(size_t)s * kd + e];
    (z ? g_B : g_A)[e] = sum;
}

// ---------------------------------------------------------------------------
// Kernel 3: Gram matrices
// ---------------------------------------------------------------------------
__global__ __launch_bounds__(KDIM)
void gram_kernel(int k, int d)
{
    __shared__ float row[DDIM];
    const int i = blockIdx.x;
    const int z = blockIdx.y;
    const int j = threadIdx.x;
    const float* src = z ? g_B : g_A;
    for (int t = j; t < d; t += KDIM) row[t] = src[i * d + t];
    __syncthreads();
    const float* aj = g_A + j * d;
    float sum = 0.f;
    #pragma unroll 8
    for (int t = 0; t < d; t++) sum = fmaf(row[t], aj[t], sum);
    (z ? g_BAt : g_AAt)[i * k + j] = sum;
}

// ---------------------------------------------------------------------------
// Kernel 4: one CTA per output row i (R8 exact — 128 parallel chains, 79 us).
// ---------------------------------------------------------------------------
__global__ __launch_bounds__(512, 1)
void solve_kernel(const float* __restrict__ evx, const float* __restrict__ evy,
                  float* __restrict__ out)
{
    __shared__ float P[KDIM * (KDIM + 1) / 2];
    __shared__ float colb[NB][KDIM];
    __shared__ float yv[KDIM];
    __shared__ float invD[KDIM];

    const int i   = blockIdx.x;
    const int tid = threadIdx.x;
    const int t   = tid & 127;
    const int q   = tid >> 7;
    const int trit = t * (t + 1) / 2;

    for (int r0 = 0; r0 < KDIM; r0 += 4) {
        int r = r0 + q;
        if (t <= r) P[r * (r + 1) / 2 + t] = g_AAt[r * KDIM + t];
    }
    if (tid < KDIM) yv[tid] = g_BAt[i * KDIM + tid];
    __syncthreads();

    if (tid < KDIM) {
        float ev = evx[tid] - evy[i];
        P[trit + tid] += LAMBDA * ev * ev;
    }
    __syncthreads();

    for (int b = 0; b < KDIM / NB; b++) {
        const int j0  = b * NB;
        const int rlo = j0 + NB;

        if (tid < 32) {
            int lrow = tid & 15;
            int row = j0 + lrow;
            int trow = row * (row + 1) / 2;
            float dreg[NB];
            float myinv = 0.f;
            #pragma unroll
            for (int c = 0; c < NB; c++)
                dreg[c] = (c <= lrow) ? P[trow + j0 + c] : 0.f;

            #pragma unroll
            for (int c = 0; c < NB; c++) {
                float dc = __shfl_sync(0xffffffffu, dreg[c], c);
                float r  = rsqrtf(dc);
                if (lrow == c)      { dreg[c] = dc * r; myinv = r; }
                else if (lrow > c)  dreg[c] *= r;
                #pragma unroll
                for (int m = c + 1; m < NB; m++) {
                    float Lmc = __shfl_sync(0xffffffffu, dreg[c], m);
                    if (lrow >= m) dreg[m] -= dreg[c] * Lmc;
                }
            }
            if (tid < 16) {
                #pragma unroll
                for (int c = 0; c < NB; c++)
                    if (c <= lrow) P[trow + j0 + c] = dreg[c];
                invD[row] = myinv;
            }
        }
        __syncthreads();

        if (rlo >= KDIM) break;

        {
            int r = rlo + tid;
            if (r < KDIM) {
                int trr = r * (r + 1) / 2;
                float a[NB];
                #pragma unroll
                for (int j = 0; j < NB; j++) a[j] = P[trr + j0 + j];
                #pragma unroll
                for (int j = 0; j < NB; j++) {
                    float v = a[j];
                    int trj = (j0 + j) * (j0 + j + 1) / 2;
                    #pragma unroll
                    for (int c = 0; c < j; c++)
                        v -= a[c] * P[trj + j0 + c];
                    a[j] = v * invD[j0 + j];
                }
                #pragma unroll
                for (int j = 0; j < NB; j++) {
                    P[trr + j0 + j] = a[j];
                    colb[j][r] = a[j];
                }
            }
        }
        __syncthreads();

        if (t >= rlo) {
            float ar[NB];
            #pragma unroll
            for (int j = 0; j < NB; j++) ar[j] = colb[j][t];
            for (int c = rlo + q; c <= t; c += 4) {
                float a2 = P[trit + c];
                #pragma unroll
                for (int j = 0; j < NB; j++) a2 -= ar[j] * colb[j][c];
                P[trit + c] = a2;
            }
        }
        __syncthreads();
    }

    for (int b = 0; b < KDIM / NB; b++) {
        const int j0 = b * NB;
        if (tid < 32) {
            int lrow = tid & 15;
            int row = j0 + lrow;
            int trow = row * (row + 1) / 2;
            float yl = yv[row];
            #pragma unroll
            for (int c = 0; c < NB; c++) {
                int rc = j0 + c;
                float t2 = yl * invD[rc];
                yl = (lrow == c) ? t2 : yl;
                float yc = __shfl_sync(0xffffffffu, yl, c);
                if (lrow > c) yl -= P[trow + rc] * yc;
            }
            if (tid < 16) yv[row] = yl;
        }
        __syncthreads();
        {
            int r = j0 + NB + tid;
            if (r < KDIM) {
                int trr = r * (r + 1) / 2;
                float a2 = yv[r];
                #pragma unroll
                for (int c = 0; c < NB; c++)
                    a2 -= P[trr + j0 + c] * yv[j0 + c];
                yv[r] = a2;
            }
        }
        __syncthreads();
    }

    for (int b = KDIM / NB - 1; b >= 0; b--) {
        const int j0 = b * NB;
        if (tid < 32) {
            int lrow = tid & 15;
            int row = j0 + lrow;
            float xl = yv[row];
            #pragma unroll
            for (int c = NB - 1; c >= 0; c--) {
                int rc = j0 + c;
                int trc = rc * (rc + 1) / 2;
                float t2 = xl * invD[rc];
                xl = (lrow == c) ? t2 : xl;
                float xc = __shfl_sync(0xffffffffu, xl, c);
                if (lrow < c) xl -= P[trc + row] * xc;
            }
            if (tid < 16) yv[row] = xl;
        }
        __syncthreads();
        {
            int r = tid;
            if (r < j0) {
                float a2 = yv[r];
                #pragma unroll
                for (int c = 0; c < NB; c++) {
                    int rc = j0 + c;
                    a2 -= P[rc * (rc + 1) / 2 + r] * yv[rc];
                }
                yv[r] = a2;
            }
        }
        __syncthreads();
    }

    if (tid < KDIM) out[i * KDIM + tid] = yv[tid];
}

// ---------------------------------------------------------------------------
// Launch
// ---------------------------------------------------------------------------
extern "C" void kernel_launch(void* const* d_in, const int* in_sizes, int n_in,
                              void* d_out, int out_size)
{
    const float* feat_x = (const float*)d_in[0];
    const float* feat_y = (const float*)d_in[1];
    const float* evals_x = (const float*)d_in[2];
    const float* evals_y = (const float*)d_in[3];
    const float* Ex = (const float*)d_in[4];
    const float* Ey = (const float*)d_in[5];

    const int  k  = in_sizes[2];                  // 128
    const long N  = (long)in_sizes[4] / k;        // 200000
    const int  d  = (int)((long)in_sizes[0] / N); // 256
    const int  kd = k * d;

    int Kc = (int)((N + NSPLIT - 1) / NSPLIT);
    Kc = ((Kc + KB - 1) / KB) * KB;

    cudaFuncSetAttribute(gemm_mma, cudaFuncAttributeMaxDynamicSharedMemorySize, SMEM_GEMM);

    dim3 ggrid(2, NSPLIT, 2);
    gemm_mma<<<ggrid, NTHREADS, SMEM_GEMM>>>(Ex, feat_x, Ey, feat_y, (int)N, d, Kc, kd);

    reduce_partials<<<(2 * kd + 255) / 256, 256>>>(kd);

    gram_kernel<<<dim3(k, 2), KDIM>>>(k, d);

    solve_kernel<<<k, 512>>>(evals_x, evals_y, (float*)d_out);
}